// round 4
// baseline (speedup 1.0000x reference)
#include <cuda_runtime.h>

#define BATCH 16
#define NL 3
#define NBL (BATCH * NL)
#define NBINS 1152          // 126 coarse exponent bins + 1024 fine bins over [0.5,1) + overflow
#define CAP 4096            // candidate capacity per (batch,layer); >= K + max bin width
#define ND 1000
#define NDET_ALL (NL * ND)
#define CHUNK 16384         // heat elements per histogram/collect block (divides all layer sizes)

// ---------------- persistent scratch (zero-initialized at module load; ----------------
// ---------------- re-zeroed by thresh_kernel each launch for graph replays) -----------
__device__ unsigned int       g_hist[NBL][NBINS];
__device__ unsigned int       g_cnt[NBL];
__device__ unsigned int       g_thresh[NBL];
__device__ unsigned long long g_cand[NBL][CAP];
__device__ float              g_det[BATCH][NL][ND][7];

// Monotone bin mapping for non-negative floats, fine-grained near the top of [0,1).
__device__ __forceinline__ int bin_of(unsigned int bits) {
    if (bits >= 0x3F800000u) return 1150;                                    // >= 1.0
    if (bits >= 0x3F000000u) return 126 + (int)((bits - 0x3F000000u) >> 13); // [0.5,1): 1024 bins
    return (int)(bits >> 23);                                                // exponent-coarse
}

// ---------------- pass 1: per-(b,layer) histogram ----------------
__global__ void __launch_bounds__(256) hist_kernel(const float* __restrict__ heat,
                                                   int n, int layer, int bpi) {
    __shared__ unsigned int sh[NBINS];
    int tid = threadIdx.x;
    for (int i = tid; i < NBINS; i += blockDim.x) sh[i] = 0u;
    __syncthreads();

    int img   = blockIdx.x / bpi;
    int chunk = blockIdx.x - img * bpi;
    const float4* p = reinterpret_cast<const float4*>(heat + (size_t)img * n) + chunk * (CHUNK / 4);

    for (int i = tid; i < CHUNK / 4; i += blockDim.x) {
        float4 v = p[i];
        atomicAdd(&sh[bin_of(__float_as_uint(v.x))], 1u);
        atomicAdd(&sh[bin_of(__float_as_uint(v.y))], 1u);
        atomicAdd(&sh[bin_of(__float_as_uint(v.z))], 1u);
        atomicAdd(&sh[bin_of(__float_as_uint(v.w))], 1u);
    }
    __syncthreads();

    int bl = img * NL + layer;
    for (int i = tid; i < NBINS; i += blockDim.x) {
        unsigned int c = sh[i];
        if (c) atomicAdd(&g_hist[bl][i], c);
    }
}

// ---------------- pass 2: find per-(b,layer) threshold; reset scratch ----------------
__global__ void __launch_bounds__(256) thresh_kernel() {
    __shared__ unsigned int sh[NBINS];
    int bl = blockIdx.x, tid = threadIdx.x;
    for (int i = tid; i < NBINS; i += blockDim.x) sh[i] = g_hist[bl][i];
    __syncthreads();

    if (tid == 0) {
        const int Ks[3] = {2000, 2000, 1024};
        int K = Ks[bl % NL];
        int bidx = NBINS - 1;
        unsigned int cum = 0;
        while (true) {
            cum += sh[bidx];
            if (cum >= (unsigned int)K || bidx == 0) break;
            --bidx;
        }
        unsigned int lb;
        if (bidx >= 1150)     lb = 0x3F800000u;
        else if (bidx >= 126) lb = 0x3F000000u + ((unsigned int)(bidx - 126) << 13);
        else                  lb = ((unsigned int)bidx) << 23;
        g_thresh[bl] = lb;
        g_cnt[bl] = 0u;
    }
    // reset histogram for the next graph replay
    for (int i = tid; i < NBINS; i += blockDim.x) g_hist[bl][i] = 0u;
}

// ---------------- pass 3: collect (value,index) candidates >= threshold ----------------
__global__ void __launch_bounds__(256) collect_kernel(const float* __restrict__ heat,
                                                      int n, int layer, int bpi) {
    int img   = blockIdx.x / bpi;
    int chunk = blockIdx.x - img * bpi;
    int bl = img * NL + layer;
    unsigned int tb = g_thresh[bl];

    const float4* p = reinterpret_cast<const float4*>(heat + (size_t)img * n) + chunk * (CHUNK / 4);
    unsigned int base_idx = (unsigned int)chunk * CHUNK;
    int tid = threadIdx.x;
    int lane = tid & 31;

    // trip count is uniform across the warp (CHUNK/4 % blockDim == 0) -> ballot safe
    for (int i = tid; i < CHUNK / 4; i += blockDim.x) {
        float4 v = p[i];
        unsigned int bx[4] = {__float_as_uint(v.x), __float_as_uint(v.y),
                              __float_as_uint(v.z), __float_as_uint(v.w)};
#pragma unroll
        for (int c = 0; c < 4; c++) {
            bool hit = (bx[c] >= tb);
            unsigned int m = __ballot_sync(0xffffffffu, hit);
            if (m) {
                int leader = __ffs(m) - 1;
                unsigned int pos = 0;
                if (lane == leader) pos = atomicAdd(&g_cnt[bl], (unsigned int)__popc(m));
                pos = __shfl_sync(0xffffffffu, pos, leader);
                if (hit) {
                    unsigned int my = pos + (unsigned int)__popc(m & ((1u << lane) - 1u));
                    if (my < CAP) {
                        unsigned int idx = base_idx + 4u * (unsigned int)i + (unsigned int)c;
                        g_cand[bl][my] =
                            ((unsigned long long)bx[c] << 32) | (unsigned int)(~idx);
                    }
                }
            }
        }
    }
}

// Descending bitonic sort of n (power of 2) u64 keys in shared memory.
__device__ __forceinline__ void bitonic_desc(unsigned long long* s, int n, int tid, int nthr) {
    for (int k = 2; k <= n; k <<= 1) {
        for (int j = k >> 1; j > 0; j >>= 1) {
            for (int i = tid; i < n; i += nthr) {
                int p = i ^ j;
                if (p > i) {
                    unsigned long long a = s[i], b = s[p];
                    if ((a < b) == ((i & k) == 0)) { s[i] = b; s[p] = a; }
                }
            }
            __syncthreads();
        }
    }
}

// ---------------- pass 4: sort candidates, decode bboxes, stable-partition to top-1000 ----------------
__global__ void __launch_bounds__(512) sortdet_kernel(const float* __restrict__ tl,
                                                      const float* __restrict__ br,
                                                      int hw, int logW, int layer,
                                                      int K, float scale) {
    __shared__ unsigned long long s[CAP];
    __shared__ int wsum[16];
    __shared__ int wtot;

    int b = blockIdx.x, tid = threadIdx.x;
    int bl = b * NL + layer;
    unsigned int cnt = g_cnt[bl];
    int m = (cnt > (unsigned int)CAP) ? CAP : (int)cnt;

    for (int i = tid; i < CAP; i += 512)
        s[i] = (i < m) ? g_cand[bl][i] : 0ull;
    __syncthreads();

    bitonic_desc(s, CAP, tid, 512);
    // s[0..K-1] is the exact sorted top-K: value desc, index asc on ties.

    const float* tlp = tl + (size_t)b * 2 * hw;
    const float* brp = br + (size_t)b * 2 * hw;
    int Wm1 = (1 << logW) - 1;

    float sc_[4], d1[4], d2[4], d3[4], d4[4];
    int flag[4];
    int tsum = 0;
#pragma unroll
    for (int u = 0; u < 4; u++) {
        int r = tid * 4 + u;
        flag[u] = 0;
        if (r < K) {
            unsigned long long key = s[r];
            unsigned int bits = (unsigned int)(key >> 32);
            unsigned int idx  = ~(unsigned int)key;
            int sp = (int)(idx & (unsigned int)(hw - 1));
            float fy = (float)(sp >> logW);
            float fx = (float)(sp & Wm1);
            float tx = tlp[sp], ty = tlp[hw + sp];
            float bx = brp[sp], by = brp[hw + sp];
            float tlx = fx - fmaf(1.5f, tx, 2.25f);
            float tly = fy - fmaf(1.5f, ty, 2.25f);
            float brx = fx + fmaf(1.5f, bx, 2.25f);
            float bry = fy + fmaf(1.5f, by, 2.25f);
            bool valid = !((brx < tlx) || (bry < tly));
            flag[u] = valid ? 1 : 0;
            sc_[u] = valid ? __uint_as_float(bits) : -1.0f;
            d1[u] = tlx * scale; d2[u] = tly * scale;
            d3[u] = brx * scale; d4[u] = bry * scale;
            tsum += flag[u];
        }
    }

    // block-wide exclusive scan of valid flags (blocked: thread t owns ranks 4t..4t+3)
    int lane = tid & 31, warp = tid >> 5;
    int incl = tsum;
#pragma unroll
    for (int off = 1; off < 32; off <<= 1) {
        int t2 = __shfl_up_sync(0xffffffffu, incl, off);
        if (lane >= off) incl += t2;
    }
    if (lane == 31) wsum[warp] = incl;
    __syncthreads();
    if (tid < 32) {
        int v = (tid < 16) ? wsum[tid] : 0;
#pragma unroll
        for (int off = 1; off < 16; off <<= 1) {
            int t2 = __shfl_up_sync(0xffffffffu, v, off);
            if (lane >= off) v += t2;
        }
        if (tid < 16) wsum[tid] = v;
        if (tid == 15) wtot = v;
    }
    __syncthreads();

    int total_valid = wtot;
    int run = (warp ? wsum[warp - 1] : 0) + (incl - tsum); // valid count before rank 4*tid
#pragma unroll
    for (int u = 0; u < 4; u++) {
        int r = tid * 4 + u;
        if (r < K) {
            // stable partition: valid first (score desc already), then invalid (-1) in rank order
            int pos = flag[u] ? run : (total_valid + (r - run));
            if (pos < ND) {
                float* d = g_det[b][layer][pos];
                d[0] = sc_[u]; d[1] = d1[u]; d[2] = d2[u];
                d[3] = d3[u];  d[4] = d4[u]; d[5] = 0.0f; d[6] = 0.0f;
            }
            run += flag[u];
        }
    }
    __syncthreads();
    // replicate det.at[:, 6, :].set(layer_idx)
    if (tid < 7) g_det[b][layer][6][tid] = (float)layer;
}

// ---------------- pass 5: merge 3x1000 -> final sorted top-1000 per batch ----------------
__global__ void __launch_bounds__(512) final_kernel(float* __restrict__ out) {
    __shared__ unsigned long long s[CAP];
    int b = blockIdx.x, tid = threadIdx.x;

    for (int i = tid; i < CAP; i += 512) {
        unsigned long long key = 0ull;
        if (i < NDET_ALL) {
            int l = i / ND, r = i - l * ND;
            unsigned int sb = __float_as_uint(g_det[b][l][r][0]);
            // monotone float->uint map (handles the -1.0 scores)
            unsigned int mp = (sb & 0x80000000u) ? ~sb : (sb | 0x80000000u);
            key = ((unsigned long long)mp << 32) | (unsigned int)(~(unsigned int)i);
        }
        s[i] = key;
    }
    __syncthreads();

    bitonic_desc(s, CAP, tid, 512);

    for (int r = tid; r < ND; r += 512) {
        unsigned int i = ~(unsigned int)s[r];
        int l = i / ND, rr = i - l * ND;
        const float* src = g_det[b][l][rr];
        float* dst = out + ((size_t)b * ND + r) * 7;
#pragma unroll
        for (int c = 0; c < 7; c++) dst[c] = src[c];
    }
}

extern "C" void kernel_launch(void* const* d_in, const int* in_sizes, int n_in,
                              void* d_out, int out_size) {
    const int   hw[3]    = {128 * 128, 64 * 64, 32 * 32};
    const int   logW[3]  = {7, 6, 5};
    const int   Kk[3]    = {2000, 2000, 1024};
    const float scale[3] = {8.0f, 16.0f, 32.0f};

    // Resolve inputs BY SIZE (metadata order is heat0, tl0, br0, heat1, tl1, br1, ...).
    // heat_l has 16*80*hw[l] elements; tl_l / br_l have 16*2*hw[l] (tl precedes br).
    const float* heat[3] = {0, 0, 0};
    const float* tl[3]   = {0, 0, 0};
    const float* br[3]   = {0, 0, 0};
    for (int i = 0; i < n_in; i++) {
        long long sz = in_sizes[i];
        for (int l = 0; l < 3; l++) {
            if (sz == (long long)BATCH * 80 * hw[l]) {
                heat[l] = (const float*)d_in[i];
            } else if (sz == (long long)BATCH * 2 * hw[l]) {
                if (!tl[l]) tl[l] = (const float*)d_in[i];
                else        br[l] = (const float*)d_in[i];
            }
        }
    }

    for (int l = 0; l < 3; l++) {
        int n = 80 * hw[l];
        int bpi = n / CHUNK;
        hist_kernel<<<BATCH * bpi, 256>>>(heat[l], n, l, bpi);
    }
    thresh_kernel<<<NBL, 256>>>();
    for (int l = 0; l < 3; l++) {
        int n = 80 * hw[l];
        int bpi = n / CHUNK;
        collect_kernel<<<BATCH * bpi, 256>>>(heat[l], n, l, bpi);
    }
    for (int l = 0; l < 3; l++)
        sortdet_kernel<<<BATCH, 512>>>(tl[l], br[l], hw[l], logW[l], l, Kk[l], scale[l]);
    final_kernel<<<BATCH, 512>>>((float*)d_out);
}

// round 5
// speedup vs baseline: 2.0047x; 2.0047x over previous
#include <cuda_runtime.h>

#define BATCH 16
#define NL 3
#define NBL (BATCH * NL)
#define NBINS 1152
#define CAP 4096
#define ND 1000
#define NDET_ALL (NL * ND)
#define CHUNK 16384
#define SPAD(i) ((i) + ((i) >> 3))   // bank-conflict padding for u64 shared arrays

// grid layout for heat-scan kernels (per-layer chunk counts)
#define BPI0 80
#define BPI1 20
#define BPI2 5
#define BLK0 (BATCH * BPI0)              // 1280
#define BLK01 (BLK0 + BATCH * BPI1)      // 1600
#define BLKALL (BLK01 + BATCH * BPI2)    // 1680

// ---------------- persistent scratch (zero at load; state self-resets each replay) ----
__device__ unsigned int       g_hist[NBL][NBINS];
__device__ unsigned int       g_cnt[NBL];       // zeroed by sortdet at end of each replay
__device__ unsigned int       g_thresh[NBL];
__device__ int                g_bad[NBL];       // rewritten fresh by check each replay
__device__ unsigned long long g_cand[NBL][CAP];
__device__ float              g_det[BATCH][NL][ND][7];

__constant__ float  c_thr[3]   = {1.0f - 3000.0f / 1310720.0f,
                                  1.0f - 3000.0f / 327680.0f,
                                  1.0f - 1500.0f / 81920.0f};
__constant__ int    c_K[3]     = {2000, 2000, 1024};

// map flat block id -> (layer, img, chunk, bl)
__device__ __forceinline__ void scan_map(int bid, int& layer, int& img, int& chunk, int& bl,
                                         int& n) {
    if (bid < BLK0)       { layer = 0; int r = bid;          img = r / BPI0; chunk = r - img * BPI0; n = 80 * 16384; }
    else if (bid < BLK01) { layer = 1; int r = bid - BLK0;   img = r / BPI1; chunk = r - img * BPI1; n = 80 * 4096; }
    else                  { layer = 2; int r = bid - BLK01;  img = r / BPI2; chunk = r - img * BPI2; n = 80 * 1024; }
    bl = img * NL + layer;
}

// Monotone bin mapping (fallback path only).
__device__ __forceinline__ int bin_of(unsigned int bits) {
    if (bits >= 0x3F800000u) return 1150;
    if (bits >= 0x3F000000u) return 126 + (int)((bits - 0x3F000000u) >> 13);
    return (int)(bits >> 23);
}

// warp-aggregated append of hits >= threshold tb over one CHUNK
__device__ __forceinline__ void collect_chunk(const float4* __restrict__ p,
                                              unsigned int base_idx, unsigned int tb, int bl) {
    int tid = threadIdx.x, lane = tid & 31;
    for (int i = tid; i < CHUNK / 4; i += 256) {
        float4 v = p[i];
        unsigned int b0 = __float_as_uint(v.x), b1 = __float_as_uint(v.y);
        unsigned int b2 = __float_as_uint(v.z), b3 = __float_as_uint(v.w);
        unsigned int mx = max(max(b0, b1), max(b2, b3));
        unsigned int anym = __ballot_sync(0xffffffffu, mx >= tb);
        if (!anym) continue;
        unsigned int bx[4] = {b0, b1, b2, b3};
#pragma unroll
        for (int c = 0; c < 4; c++) {
            bool hit = (bx[c] >= tb);
            unsigned int m = __ballot_sync(0xffffffffu, hit);
            if (m) {
                int leader = __ffs(m) - 1;
                unsigned int pos = 0;
                if (lane == leader) pos = atomicAdd(&g_cnt[bl], (unsigned int)__popc(m));
                pos = __shfl_sync(0xffffffffu, pos, leader);
                if (hit) {
                    unsigned int my = pos + (unsigned int)__popc(m & ((1u << lane) - 1u));
                    if (my < CAP) {
                        unsigned int idx = base_idx + 4u * (unsigned int)i + (unsigned int)c;
                        g_cand[bl][my] = ((unsigned long long)bx[c] << 32) | (unsigned int)(~idx);
                    }
                }
            }
        }
    }
}

// ---------------- pass 1: single-pass collect with static thresholds ----------------
__global__ void __launch_bounds__(256) collectA_kernel(const float* __restrict__ h0,
                                                       const float* __restrict__ h1,
                                                       const float* __restrict__ h2) {
    int layer, img, chunk, bl, n;
    scan_map(blockIdx.x, layer, img, chunk, bl, n);
    const float* heat = (layer == 0) ? h0 : (layer == 1) ? h1 : h2;
    const float4* p = reinterpret_cast<const float4*>(heat + (size_t)img * n) + chunk * (CHUNK / 4);
    collect_chunk(p, (unsigned int)chunk * CHUNK, __float_as_uint(c_thr[layer]), bl);
}

// ---------------- pass 2: validate counts; flag fallback ----------------
__global__ void check_kernel() {
    int bl = threadIdx.x;
    if (bl < NBL) {
        unsigned int cnt = g_cnt[bl];
        int bad = (cnt < (unsigned int)c_K[bl % NL]) || (cnt > CAP);
        g_bad[bl] = bad;
        if (bad) g_cnt[bl] = 0u;
    }
}

// ---------------- gated fallback: exact hist -> threshold -> re-collect ----------------
__global__ void __launch_bounds__(256) hist_gated_kernel(const float* __restrict__ h0,
                                                         const float* __restrict__ h1,
                                                         const float* __restrict__ h2) {
    int layer, img, chunk, bl, n;
    scan_map(blockIdx.x, layer, img, chunk, bl, n);
    if (!g_bad[bl]) return;

    __shared__ unsigned int sh[NBINS];
    int tid = threadIdx.x;
    for (int i = tid; i < NBINS; i += 256) sh[i] = 0u;
    __syncthreads();

    const float* heat = (layer == 0) ? h0 : (layer == 1) ? h1 : h2;
    const float4* p = reinterpret_cast<const float4*>(heat + (size_t)img * n) + chunk * (CHUNK / 4);
    for (int i = tid; i < CHUNK / 4; i += 256) {
        float4 v = p[i];
        atomicAdd(&sh[bin_of(__float_as_uint(v.x))], 1u);
        atomicAdd(&sh[bin_of(__float_as_uint(v.y))], 1u);
        atomicAdd(&sh[bin_of(__float_as_uint(v.z))], 1u);
        atomicAdd(&sh[bin_of(__float_as_uint(v.w))], 1u);
    }
    __syncthreads();
    for (int i = tid; i < NBINS; i += 256) {
        unsigned int c = sh[i];
        if (c) atomicAdd(&g_hist[bl][i], c);
    }
}

__global__ void __launch_bounds__(256) thresh_gated_kernel() {
    int bl = blockIdx.x, tid = threadIdx.x;
    if (!g_bad[bl]) return;
    __shared__ unsigned int sh[NBINS];
    for (int i = tid; i < NBINS; i += 256) sh[i] = g_hist[bl][i];
    __syncthreads();
    if (tid == 0) {
        int K = c_K[bl % NL];
        int bidx = NBINS - 1;
        unsigned int cum = 0;
        while (true) {
            cum += sh[bidx];
            if (cum >= (unsigned int)K || bidx == 0) break;
            --bidx;
        }
        unsigned int lb;
        if (bidx >= 1150)     lb = 0x3F800000u;
        else if (bidx >= 126) lb = 0x3F000000u + ((unsigned int)(bidx - 126) << 13);
        else                  lb = ((unsigned int)bidx) << 23;
        g_thresh[bl] = lb;
    }
    for (int i = tid; i < NBINS; i += 256) g_hist[bl][i] = 0u;  // reset for next replay
}

__global__ void __launch_bounds__(256) collectB_gated_kernel(const float* __restrict__ h0,
                                                             const float* __restrict__ h1,
                                                             const float* __restrict__ h2) {
    int layer, img, chunk, bl, n;
    scan_map(blockIdx.x, layer, img, chunk, bl, n);
    if (!g_bad[bl]) return;
    const float* heat = (layer == 0) ? h0 : (layer == 1) ? h1 : h2;
    const float4* p = reinterpret_cast<const float4*>(heat + (size_t)img * n) + chunk * (CHUNK / 4);
    collect_chunk(p, (unsigned int)chunk * CHUNK, g_thresh[bl], bl);
}

// ---------------- register-blocked, padded bitonic sort (descending) ----------------
__device__ __forceinline__ void ce(unsigned long long& a, unsigned long long& b, bool dir) {
    if ((a < b) == dir) { unsigned long long t = a; a = b; b = t; }
}

// s is a PADDED shared array (index with SPAD). n in {2048, 4096}. 512 threads.
__device__ void bitonic_desc_opt(unsigned long long* s, int n, int tid) {
    // stage A: k = 2, 4, 8 fully in registers (thread owns 8 contiguous keys)
    for (int t8 = tid; t8 < (n >> 3); t8 += 512) {
        int g = t8 << 3;
        unsigned long long v[8];
#pragma unroll
        for (int x = 0; x < 8; x++) v[x] = s[SPAD(g + x)];
        // k=2 (j=1)
        ce(v[0], v[1], true);  ce(v[2], v[3], false);
        ce(v[4], v[5], true);  ce(v[6], v[7], false);
        // k=4 (j=2,1)
        ce(v[0], v[2], true);  ce(v[1], v[3], true);
        ce(v[4], v[6], false); ce(v[5], v[7], false);
        ce(v[0], v[1], true);  ce(v[2], v[3], true);
        ce(v[4], v[5], false); ce(v[6], v[7], false);
        // k=8 (j=4,2,1), direction constant per 8-block
        bool d8 = ((g & 8) == 0);
        ce(v[0], v[4], d8); ce(v[1], v[5], d8); ce(v[2], v[6], d8); ce(v[3], v[7], d8);
        ce(v[0], v[2], d8); ce(v[1], v[3], d8); ce(v[4], v[6], d8); ce(v[5], v[7], d8);
        ce(v[0], v[1], d8); ce(v[2], v[3], d8); ce(v[4], v[5], d8); ce(v[6], v[7], d8);
#pragma unroll
        for (int x = 0; x < 8; x++) s[SPAD(g + x)] = v[x];
    }
    __syncthreads();

    for (int k = 16; k <= n; k <<= 1) {
        for (int j = k >> 1; j >= 8; j >>= 1) {
            for (int idx = tid; idx < (n >> 1); idx += 512) {
                int i = ((idx & ~(j - 1)) << 1) | (idx & (j - 1));
                int p = i + j;
                bool dir = ((i & k) == 0);
                unsigned long long a = s[SPAD(i)], b = s[SPAD(p)];
                if ((a < b) == dir) { s[SPAD(i)] = b; s[SPAD(p)] = a; }
            }
            __syncthreads();
        }
        // j = 4,2,1 in registers; dir constant per 8-block since k >= 16
        for (int t8 = tid; t8 < (n >> 3); t8 += 512) {
            int g = t8 << 3;
            bool dir = ((g & k) == 0);
            unsigned long long v[8];
#pragma unroll
            for (int x = 0; x < 8; x++) v[x] = s[SPAD(g + x)];
            ce(v[0], v[4], dir); ce(v[1], v[5], dir); ce(v[2], v[6], dir); ce(v[3], v[7], dir);
            ce(v[0], v[2], dir); ce(v[1], v[3], dir); ce(v[4], v[6], dir); ce(v[5], v[7], dir);
            ce(v[0], v[1], dir); ce(v[2], v[3], dir); ce(v[4], v[5], dir); ce(v[6], v[7], dir);
#pragma unroll
            for (int x = 0; x < 8; x++) s[SPAD(g + x)] = v[x];
        }
        __syncthreads();
    }
}

// ---------------- pass 3: sort candidates, decode, stable-partition -> per-layer det ----
__global__ void __launch_bounds__(512) sortdet_kernel(const float* __restrict__ tl0,
                                                      const float* __restrict__ br0,
                                                      const float* __restrict__ tl1,
                                                      const float* __restrict__ br1,
                                                      const float* __restrict__ tl2,
                                                      const float* __restrict__ br2) {
    __shared__ unsigned long long s[SPAD(CAP)];
    __shared__ int wsum[16];
    __shared__ int wtot;

    int bl = blockIdx.x, tid = threadIdx.x;
    int b = bl / NL, layer = bl % NL;

    const int   hws[3]   = {16384, 4096, 1024};
    const int   logWs[3] = {7, 6, 5};
    const float scs[3]   = {8.0f, 16.0f, 32.0f};
    int hw = hws[layer], logW = logWs[layer], K = c_K[layer];
    float scale = scs[layer];
    const float* tl = (layer == 0) ? tl0 : (layer == 1) ? tl1 : tl2;
    const float* br = (layer == 0) ? br0 : (layer == 1) ? br1 : br2;

    unsigned int cnt = g_cnt[bl];
    int m = (cnt > (unsigned int)CAP) ? CAP : (int)cnt;
    int n = (m <= 2048 && K <= 2048) ? 2048 : CAP;

    for (int i = tid; i < n; i += 512)
        s[SPAD(i)] = (i < m) ? g_cand[bl][i] : 0ull;
    __syncthreads();

    bitonic_desc_opt(s, n, tid);
    // s[0..K-1] = exact sorted top-K: value desc, index asc on ties.

    const float* tlp = tl + (size_t)b * 2 * hw;
    const float* brp = br + (size_t)b * 2 * hw;
    int Wm1 = (1 << logW) - 1;

    float sc_[4], d1[4], d2[4], d3[4], d4[4];
    int flag[4];
    int tsum = 0;
#pragma unroll
    for (int u = 0; u < 4; u++) {
        int r = tid * 4 + u;
        flag[u] = 0;
        if (r < K) {
            unsigned long long key = s[SPAD(r)];
            unsigned int bits = (unsigned int)(key >> 32);
            unsigned int idx  = ~(unsigned int)key;
            int sp = (int)(idx & (unsigned int)(hw - 1));
            float fy = (float)(sp >> logW);
            float fx = (float)(sp & Wm1);
            float tx = tlp[sp], ty = tlp[hw + sp];
            float bx = brp[sp], by = brp[hw + sp];
            float tlx = fx - fmaf(1.5f, tx, 2.25f);
            float tly = fy - fmaf(1.5f, ty, 2.25f);
            float brx = fx + fmaf(1.5f, bx, 2.25f);
            float bry = fy + fmaf(1.5f, by, 2.25f);
            bool valid = !((brx < tlx) || (bry < tly));
            flag[u] = valid ? 1 : 0;
            sc_[u] = valid ? __uint_as_float(bits) : -1.0f;
            d1[u] = tlx * scale; d2[u] = tly * scale;
            d3[u] = brx * scale; d4[u] = bry * scale;
            tsum += flag[u];
        }
    }

    // block exclusive scan of valid flags (thread t owns ranks 4t..4t+3)
    int lane = tid & 31, warp = tid >> 5;
    int incl = tsum;
#pragma unroll
    for (int off = 1; off < 32; off <<= 1) {
        int t2 = __shfl_up_sync(0xffffffffu, incl, off);
        if (lane >= off) incl += t2;
    }
    if (lane == 31) wsum[warp] = incl;
    __syncthreads();
    if (tid < 32) {
        int v = (tid < 16) ? wsum[tid] : 0;
#pragma unroll
        for (int off = 1; off < 16; off <<= 1) {
            int t2 = __shfl_up_sync(0xffffffffu, v, off);
            if (lane >= off) v += t2;
        }
        if (tid < 16) wsum[tid] = v;
        if (tid == 15) wtot = v;
    }
    __syncthreads();

    int total_valid = wtot;
    int run = (warp ? wsum[warp - 1] : 0) + (incl - tsum);
#pragma unroll
    for (int u = 0; u < 4; u++) {
        int r = tid * 4 + u;
        if (r < K) {
            int pos = flag[u] ? run : (total_valid + (r - run));
            if (pos < ND) {
                float* d = g_det[b][layer][pos];
                d[0] = sc_[u]; d[1] = d1[u]; d[2] = d2[u];
                d[3] = d3[u];  d[4] = d4[u]; d[5] = 0.0f; d[6] = 0.0f;
            }
            run += flag[u];
        }
    }
    __syncthreads();
    if (tid < 7) g_det[b][layer][6][tid] = (float)layer;   // det.at[:,6,:] = layer
    if (tid == 0) g_cnt[bl] = 0u;                          // reset for next replay
}

// ---------------- pass 4: merge 3x1000 -> final sorted top-1000 per batch ----------------
__global__ void __launch_bounds__(512) final_kernel(float* __restrict__ out) {
    __shared__ unsigned long long s[SPAD(CAP)];
    int b = blockIdx.x, tid = threadIdx.x;

    for (int i = tid; i < CAP; i += 512) {
        unsigned long long key = 0ull;
        if (i < NDET_ALL) {
            int l = i / ND, r = i - l * ND;
            unsigned int sb = __float_as_uint(g_det[b][l][r][0]);
            unsigned int mp = (sb & 0x80000000u) ? ~sb : (sb | 0x80000000u);
            key = ((unsigned long long)mp << 32) | (unsigned int)(~(unsigned int)i);
        }
        s[SPAD(i)] = key;
    }
    __syncthreads();

    bitonic_desc_opt(s, CAP, tid);

    for (int r = tid; r < ND; r += 512) {
        unsigned int i = ~(unsigned int)s[SPAD(r)];
        int l = i / ND, rr = i - l * ND;
        const float* src = g_det[b][l][rr];
        float* dst = out + ((size_t)b * ND + r) * 7;
#pragma unroll
        for (int c = 0; c < 7; c++) dst[c] = src[c];
    }
}

extern "C" void kernel_launch(void* const* d_in, const int* in_sizes, int n_in,
                              void* d_out, int out_size) {
    const int hw[3] = {16384, 4096, 1024};

    // Resolve inputs BY SIZE (metadata order is heat0, tl0, br0, heat1, ...).
    const float* heat[3] = {0, 0, 0};
    const float* tl[3]   = {0, 0, 0};
    const float* br[3]   = {0, 0, 0};
    for (int i = 0; i < n_in; i++) {
        long long sz = in_sizes[i];
        for (int l = 0; l < 3; l++) {
            if (sz == (long long)BATCH * 80 * hw[l]) {
                heat[l] = (const float*)d_in[i];
            } else if (sz == (long long)BATCH * 2 * hw[l]) {
                if (!tl[l]) tl[l] = (const float*)d_in[i];
                else        br[l] = (const float*)d_in[i];
            }
        }
    }

    collectA_kernel<<<BLKALL, 256>>>(heat[0], heat[1], heat[2]);
    check_kernel<<<1, 64>>>();
    hist_gated_kernel<<<BLKALL, 256>>>(heat[0], heat[1], heat[2]);
    thresh_gated_kernel<<<NBL, 256>>>();
    collectB_gated_kernel<<<BLKALL, 256>>>(heat[0], heat[1], heat[2]);
    sortdet_kernel<<<NBL, 512>>>(tl[0], br[0], tl[1], br[1], tl[2], br[2]);
    final_kernel<<<BATCH, 512>>>((float*)d_out);
}

// round 6
// speedup vs baseline: 2.4830x; 1.2386x over previous
#include <cuda_runtime.h>

#define BATCH 16
#define NL 3
#define NBL (BATCH * NL)
#define NBINS 1152
#define CAP 4096
#define ND 1000
#define CHUNK 16384
#define SPAD(i) ((i) + ((i) >> 3))   // bank-conflict padding for u64 shared arrays

// grid layout for collectA (per-layer chunk counts)
#define BPI0 80
#define BPI1 20
#define BPI2 5
#define BLK0 (BATCH * BPI0)              // 1280
#define BLK01 (BLK0 + BATCH * BPI1)      // 1600
#define BLKALL (BLK01 + BATCH * BPI2)    // 1680

// ---------------- persistent scratch (zero at load; self-resetting each replay) -------
__device__ unsigned int       g_cnt[NBL];   // zeroed by sortdet at end of each replay
__device__ unsigned long long g_cand[NBL][CAP];
__device__ float              g_det[BATCH][NL][ND][7];

__constant__ float c_thr[3] = {1.0f - 3000.0f / 1310720.0f,
                               1.0f - 3000.0f / 327680.0f,
                               1.0f - 1500.0f / 81920.0f};
__constant__ int   c_K[3]   = {2000, 2000, 1024};

// Monotone bin mapping (fallback path only): fine bins over [0.5,1).
__device__ __forceinline__ int bin_of(unsigned int bits) {
    if (bits >= 0x3F800000u) return 1150;
    if (bits >= 0x3F000000u) return 126 + (int)((bits - 0x3F000000u) >> 13);
    return (int)(bits >> 23);
}

// warp-aggregated append of hits >= tb over n4 float4s (n4 % blockDim == 0)
template <int NT>
__device__ __forceinline__ void collect_span(const float4* __restrict__ p, int n4,
                                             unsigned int tb, int bl) {
    int tid = threadIdx.x, lane = tid & 31;
    for (int i = tid; i < n4; i += NT) {
        float4 v = p[i];
        unsigned int b0 = __float_as_uint(v.x), b1 = __float_as_uint(v.y);
        unsigned int b2 = __float_as_uint(v.z), b3 = __float_as_uint(v.w);
        unsigned int mx = max(max(b0, b1), max(b2, b3));
        if (!__ballot_sync(0xffffffffu, mx >= tb)) continue;
        unsigned int bx[4] = {b0, b1, b2, b3};
#pragma unroll
        for (int c = 0; c < 4; c++) {
            bool hit = (bx[c] >= tb);
            unsigned int m = __ballot_sync(0xffffffffu, hit);
            if (m) {
                int leader = __ffs(m) - 1;
                unsigned int pos = 0;
                if (lane == leader) pos = atomicAdd(&g_cnt[bl], (unsigned int)__popc(m));
                pos = __shfl_sync(0xffffffffu, pos, leader);
                if (hit) {
                    unsigned int my = pos + (unsigned int)__popc(m & ((1u << lane) - 1u));
                    if (my < CAP) {
                        unsigned int idx = 4u * (unsigned int)i + (unsigned int)c;
                        g_cand[bl][my] = ((unsigned long long)bx[c] << 32) | (unsigned int)(~idx);
                    }
                }
            }
        }
    }
}

// ---------------- pass 1: single-pass collect with static thresholds ----------------
__global__ void __launch_bounds__(256) collectA_kernel(const float* __restrict__ h0,
                                                       const float* __restrict__ h1,
                                                       const float* __restrict__ h2) {
    int bid = blockIdx.x, layer, img, chunk, n;
    const float* heat;
    if (bid < BLK0)       { layer = 0; int r = bid;         img = r / BPI0; chunk = r - img * BPI0; n = 80 * 16384; heat = h0; }
    else if (bid < BLK01) { layer = 1; int r = bid - BLK0;  img = r / BPI1; chunk = r - img * BPI1; n = 80 * 4096;  heat = h1; }
    else                  { layer = 2; int r = bid - BLK01; img = r / BPI2; chunk = r - img * BPI2; n = 80 * 1024;  heat = h2; }
    int bl = img * NL + layer;
    unsigned int tb = __float_as_uint(c_thr[layer]);

    const float4* p = reinterpret_cast<const float4*>(heat + (size_t)img * n) + chunk * (CHUNK / 4);
    unsigned int base_idx = (unsigned int)chunk * CHUNK;
    int tid = threadIdx.x, lane = tid & 31;
    for (int i = tid; i < CHUNK / 4; i += 256) {
        float4 v = p[i];
        unsigned int b0 = __float_as_uint(v.x), b1 = __float_as_uint(v.y);
        unsigned int b2 = __float_as_uint(v.z), b3 = __float_as_uint(v.w);
        unsigned int mx = max(max(b0, b1), max(b2, b3));
        if (!__ballot_sync(0xffffffffu, mx >= tb)) continue;
        unsigned int bx[4] = {b0, b1, b2, b3};
#pragma unroll
        for (int c = 0; c < 4; c++) {
            bool hit = (bx[c] >= tb);
            unsigned int m = __ballot_sync(0xffffffffu, hit);
            if (m) {
                int leader = __ffs(m) - 1;
                unsigned int pos = 0;
                if (lane == leader) pos = atomicAdd(&g_cnt[bl], (unsigned int)__popc(m));
                pos = __shfl_sync(0xffffffffu, pos, leader);
                if (hit) {
                    unsigned int my = pos + (unsigned int)__popc(m & ((1u << lane) - 1u));
                    if (my < CAP) {
                        unsigned int idx = base_idx + 4u * (unsigned int)i + (unsigned int)c;
                        g_cand[bl][my] = ((unsigned long long)bx[c] << 32) | (unsigned int)(~idx);
                    }
                }
            }
        }
    }
}

// ---------------- register-blocked, padded bitonic sort (descending), NT threads ------
__device__ __forceinline__ void ce(unsigned long long& a, unsigned long long& b, bool dir) {
    if ((a < b) == dir) { unsigned long long t = a; a = b; b = t; }
}

template <int NT>
__device__ void bitonic_desc_opt(unsigned long long* s, int n, int tid) {
    // k = 2, 4, 8 fully in registers (8 contiguous keys per work item)
    for (int t8 = tid; t8 < (n >> 3); t8 += NT) {
        int g = t8 << 3;
        unsigned long long v[8];
#pragma unroll
        for (int x = 0; x < 8; x++) v[x] = s[SPAD(g + x)];
        ce(v[0], v[1], true);  ce(v[2], v[3], false);
        ce(v[4], v[5], true);  ce(v[6], v[7], false);
        ce(v[0], v[2], true);  ce(v[1], v[3], true);
        ce(v[4], v[6], false); ce(v[5], v[7], false);
        ce(v[0], v[1], true);  ce(v[2], v[3], true);
        ce(v[4], v[5], false); ce(v[6], v[7], false);
        bool d8 = ((g & 8) == 0);
        ce(v[0], v[4], d8); ce(v[1], v[5], d8); ce(v[2], v[6], d8); ce(v[3], v[7], d8);
        ce(v[0], v[2], d8); ce(v[1], v[3], d8); ce(v[4], v[6], d8); ce(v[5], v[7], d8);
        ce(v[0], v[1], d8); ce(v[2], v[3], d8); ce(v[4], v[5], d8); ce(v[6], v[7], d8);
#pragma unroll
        for (int x = 0; x < 8; x++) s[SPAD(g + x)] = v[x];
    }
    __syncthreads();

    for (int k = 16; k <= n; k <<= 1) {
        for (int j = k >> 1; j >= 8; j >>= 1) {
            for (int idx = tid; idx < (n >> 1); idx += NT) {
                int i = ((idx & ~(j - 1)) << 1) | (idx & (j - 1));
                int p = i + j;
                bool dir = ((i & k) == 0);
                unsigned long long a = s[SPAD(i)], b = s[SPAD(p)];
                if ((a < b) == dir) { s[SPAD(i)] = b; s[SPAD(p)] = a; }
            }
            __syncthreads();
        }
        for (int t8 = tid; t8 < (n >> 3); t8 += NT) {
            int g = t8 << 3;
            bool dir = ((g & k) == 0);
            unsigned long long v[8];
#pragma unroll
            for (int x = 0; x < 8; x++) v[x] = s[SPAD(g + x)];
            ce(v[0], v[4], dir); ce(v[1], v[5], dir); ce(v[2], v[6], dir); ce(v[3], v[7], dir);
            ce(v[0], v[2], dir); ce(v[1], v[3], dir); ce(v[4], v[6], dir); ce(v[5], v[7], dir);
            ce(v[0], v[1], dir); ce(v[2], v[3], dir); ce(v[4], v[5], dir); ce(v[6], v[7], dir);
#pragma unroll
            for (int x = 0; x < 8; x++) s[SPAD(g + x)] = v[x];
        }
        __syncthreads();
    }
}

// ---------------- pass 2: (gated exact fallback) + sort + decode + partition ----------
__global__ void __launch_bounds__(1024) sortdet_kernel(const float* __restrict__ h0,
                                                       const float* __restrict__ h1,
                                                       const float* __restrict__ h2,
                                                       const float* __restrict__ tl0,
                                                       const float* __restrict__ br0,
                                                       const float* __restrict__ tl1,
                                                       const float* __restrict__ br1,
                                                       const float* __restrict__ tl2,
                                                       const float* __restrict__ br2) {
    __shared__ unsigned long long s[SPAD(CAP)];
    __shared__ unsigned int sh_hist[NBINS];
    __shared__ unsigned int sh_tb;
    __shared__ int wsum[32];
    __shared__ int wtot;

    int bl = blockIdx.x, tid = threadIdx.x;
    int b = bl / NL, layer = bl % NL;

    const int   hws[3]   = {16384, 4096, 1024};
    const int   logWs[3] = {7, 6, 5};
    const float scs[3]   = {8.0f, 16.0f, 32.0f};
    int hw = hws[layer], logW = logWs[layer], K = c_K[layer];
    float scale = scs[layer];
    const float* heat = (layer == 0) ? h0 : (layer == 1) ? h1 : h2;
    const float* tl   = (layer == 0) ? tl0 : (layer == 1) ? tl1 : tl2;
    const float* br   = (layer == 0) ? br0 : (layer == 1) ? br1 : br2;
    int n_layer = 80 * hw;

    unsigned int cnt = g_cnt[bl];
    if (cnt < (unsigned int)K || cnt > CAP) {
        // -------- exact fallback, fully within this block --------
        for (int i = tid; i < NBINS; i += 1024) sh_hist[i] = 0u;
        __syncthreads();
        const float4* p = reinterpret_cast<const float4*>(heat + (size_t)b * n_layer);
        int n4 = n_layer >> 2;
        for (int i = tid; i < n4; i += 1024) {
            float4 v = p[i];
            atomicAdd(&sh_hist[bin_of(__float_as_uint(v.x))], 1u);
            atomicAdd(&sh_hist[bin_of(__float_as_uint(v.y))], 1u);
            atomicAdd(&sh_hist[bin_of(__float_as_uint(v.z))], 1u);
            atomicAdd(&sh_hist[bin_of(__float_as_uint(v.w))], 1u);
        }
        __syncthreads();
        if (tid == 0) {
            int bidx = NBINS - 1;
            unsigned int cum = 0;
            while (true) {
                cum += sh_hist[bidx];
                if (cum >= (unsigned int)K || bidx == 0) break;
                --bidx;
            }
            unsigned int lb;
            if (bidx >= 1150)     lb = 0x3F800000u;
            else if (bidx >= 126) lb = 0x3F000000u + ((unsigned int)(bidx - 126) << 13);
            else                  lb = ((unsigned int)bidx) << 23;
            sh_tb = lb;
            g_cnt[bl] = 0u;
        }
        __syncthreads();
        collect_span<1024>(p, n4, sh_tb, bl);
        __syncthreads();
        cnt = g_cnt[bl];
    }

    int m = (cnt > (unsigned int)CAP) ? CAP : (int)cnt;
    int n = (m <= 2048) ? 2048 : CAP;   // K <= 2048 always

    for (int i = tid; i < n; i += 1024)
        s[SPAD(i)] = (i < m) ? g_cand[bl][i] : 0ull;
    __syncthreads();

    bitonic_desc_opt<1024>(s, n, tid);
    // s[0..K-1] = exact sorted top-K: value desc, index asc on ties.

    const float* tlp = tl + (size_t)b * 2 * hw;
    const float* brp = br + (size_t)b * 2 * hw;
    int Wm1 = (1 << logW) - 1;

    float sc_[2], d1[2], d2[2], d3[2], d4[2];
    int flag[2];
    int tsum = 0;
#pragma unroll
    for (int u = 0; u < 2; u++) {
        int r = tid * 2 + u;
        flag[u] = 0;
        if (r < K) {
            unsigned long long key = s[SPAD(r)];
            unsigned int bits = (unsigned int)(key >> 32);
            unsigned int idx  = ~(unsigned int)key;
            int sp = (int)(idx & (unsigned int)(hw - 1));
            float fy = (float)(sp >> logW);
            float fx = (float)(sp & Wm1);
            float tx = tlp[sp], ty = tlp[hw + sp];
            float bx = brp[sp], by = brp[hw + sp];
            float tlx = fx - fmaf(1.5f, tx, 2.25f);
            float tly = fy - fmaf(1.5f, ty, 2.25f);
            float brx = fx + fmaf(1.5f, bx, 2.25f);
            float bry = fy + fmaf(1.5f, by, 2.25f);
            bool valid = !((brx < tlx) || (bry < tly));
            flag[u] = valid ? 1 : 0;
            sc_[u] = valid ? __uint_as_float(bits) : -1.0f;
            d1[u] = tlx * scale; d2[u] = tly * scale;
            d3[u] = brx * scale; d4[u] = bry * scale;
            tsum += flag[u];
        }
    }

    // block exclusive scan of valid flags (thread t owns ranks 2t, 2t+1)
    int lane = tid & 31, warp = tid >> 5;
    int incl = tsum;
#pragma unroll
    for (int off = 1; off < 32; off <<= 1) {
        int t2 = __shfl_up_sync(0xffffffffu, incl, off);
        if (lane >= off) incl += t2;
    }
    if (lane == 31) wsum[warp] = incl;
    __syncthreads();
    if (tid < 32) {
        int v = wsum[tid];
#pragma unroll
        for (int off = 1; off < 32; off <<= 1) {
            int t2 = __shfl_up_sync(0xffffffffu, v, off);
            if (lane >= off) v += t2;
        }
        wsum[tid] = v;
        if (tid == 31) wtot = v;
    }
    __syncthreads();

    int total_valid = wtot;
    int run = (warp ? wsum[warp - 1] : 0) + (incl - tsum);
#pragma unroll
    for (int u = 0; u < 2; u++) {
        int r = tid * 2 + u;
        if (r < K) {
            int pos = flag[u] ? run : (total_valid + (r - run));
            if (pos < ND) {
                float* d = g_det[b][layer][pos];
                d[0] = sc_[u]; d[1] = d1[u]; d[2] = d2[u];
                d[3] = d3[u];  d[4] = d4[u]; d[5] = 0.0f; d[6] = 0.0f;
            }
            run += flag[u];
        }
    }
    __syncthreads();
    if (tid < 7) g_det[b][layer][6][tid] = (float)layer;   // det.at[:,6,:] = layer
    if (tid == 0) g_cnt[bl] = 0u;                          // reset for next replay
}

// ---------------- pass 3: 3-way sorted merge by ranking (no sort) ----------------
// Each per-layer segment is descending in key except the row-6 overwrite; treat it as
// a sorted 999-list with a hole at index 6 plus one singleton. Keys are unique.
__global__ void __launch_bounds__(1024) final_kernel(float* __restrict__ out) {
    __shared__ unsigned long long keys[NL * ND];
    __shared__ unsigned long long ovk[NL];
    int b = blockIdx.x, tid = threadIdx.x;

    for (int i = tid; i < NL * ND; i += 1024) {
        int l = i / ND, r = i - l * ND;
        unsigned int sb = __float_as_uint(g_det[b][l][r][0]);
        unsigned int mp = (sb & 0x80000000u) ? ~sb : (sb | 0x80000000u);  // monotone map
        keys[i] = ((unsigned long long)mp << 32) | (unsigned int)(~(unsigned int)i);
    }
    __syncthreads();
    if (tid < NL) ovk[tid] = keys[tid * ND + 6];
    __syncthreads();

    for (int e = tid; e < NL * ND; e += 1024) {
        unsigned long long my = keys[e];
        int rank = 0;
#pragma unroll
        for (int l = 0; l < NL; l++) {
            // count strictly greater in holed (999-elem) descending list of segment l
            int lo = 0, hi = ND - 1;
            int base = l * ND;
            while (lo < hi) {
                int mid = (lo + hi) >> 1;
                int ph = mid + (mid >= 6);
                if (keys[base + ph] > my) lo = mid + 1; else hi = mid;
            }
            rank += lo + (ovk[l] > my ? 1 : 0);
        }
        if (rank < ND) {
            int l = e / ND, r = e - l * ND;
            const float* src = g_det[b][l][r];
            float* dst = out + ((size_t)b * ND + rank) * 7;
#pragma unroll
            for (int c = 0; c < 7; c++) dst[c] = src[c];
        }
    }
}

extern "C" void kernel_launch(void* const* d_in, const int* in_sizes, int n_in,
                              void* d_out, int out_size) {
    const int hw[3] = {16384, 4096, 1024};

    // Resolve inputs BY SIZE (metadata order is heat0, tl0, br0, heat1, ...).
    const float* heat[3] = {0, 0, 0};
    const float* tl[3]   = {0, 0, 0};
    const float* br[3]   = {0, 0, 0};
    for (int i = 0; i < n_in; i++) {
        long long sz = in_sizes[i];
        for (int l = 0; l < 3; l++) {
            if (sz == (long long)BATCH * 80 * hw[l]) {
                heat[l] = (const float*)d_in[i];
            } else if (sz == (long long)BATCH * 2 * hw[l]) {
                if (!tl[l]) tl[l] = (const float*)d_in[i];
                else        br[l] = (const float*)d_in[i];
            }
        }
    }

    collectA_kernel<<<BLKALL, 256>>>(heat[0], heat[1], heat[2]);
    sortdet_kernel<<<NBL, 1024>>>(heat[0], heat[1], heat[2],
                                  tl[0], br[0], tl[1], br[1], tl[2], br[2]);
    final_kernel<<<BATCH, 1024>>>((float*)d_out);
}

// round 7
// speedup vs baseline: 2.4848x; 1.0007x over previous
#include <cuda_runtime.h>

#define BATCH 16
#define NL 3
#define NBL (BATCH * NL)
#define NBINS 1152
#define CAP 4096
#define ND 1000
#define CHUNK 16384
#define SPAD(i) ((i) + ((i) >> 3))   // bank-conflict padding for u64 shared arrays

// grid layout for collectA (per-layer chunk counts)
#define BPI0 80
#define BPI1 20
#define BPI2 5
#define BLK0 (BATCH * BPI0)              // 1280
#define BLK01 (BLK0 + BATCH * BPI1)      // 1600
#define BLKALL (BLK01 + BATCH * BPI2)    // 1680

// ---------------- persistent scratch (zero at load; self-resetting each replay) -------
__device__ unsigned int       g_cnt[NBL];   // zeroed by sortdet at end of each replay
__device__ unsigned long long g_cand[NBL][CAP];
__device__ float              g_det[BATCH][NL][ND][7];

__constant__ float c_thr[3] = {1.0f - 3000.0f / 1310720.0f,
                               1.0f - 3000.0f / 327680.0f,
                               1.0f - 1500.0f / 81920.0f};
__constant__ int   c_K[3]   = {2000, 2000, 1024};

// Monotone bin mapping (fallback path only): fine bins over [0.5,1).
__device__ __forceinline__ int bin_of(unsigned int bits) {
    if (bits >= 0x3F800000u) return 1150;
    if (bits >= 0x3F000000u) return 126 + (int)((bits - 0x3F000000u) >> 13);
    return (int)(bits >> 23);
}

// per-value append (hits are rare; plain global atomics are cheapest)
__device__ __forceinline__ void try_append(unsigned int bits, unsigned int idx,
                                           unsigned int tb, int bl) {
    if (bits >= tb) {
        unsigned int pos = atomicAdd(&g_cnt[bl], 1u);
        if (pos < CAP)
            g_cand[bl][pos] = ((unsigned long long)bits << 32) | (unsigned int)(~idx);
    }
}

// ---------------- pass 1: single-pass collect with static thresholds ----------------
// Hot loop: 8 independent coalesced LDG.128 per thread per iteration (MLP ~8),
// no warp votes; hit path taken ~0.23% of values.
__global__ void __launch_bounds__(256) collectA_kernel(const float* __restrict__ h0,
                                                       const float* __restrict__ h1,
                                                       const float* __restrict__ h2) {
    int bid = blockIdx.x, layer, img, chunk, n;
    const float* heat;
    if (bid < BLK0)       { layer = 0; int r = bid;         img = r / BPI0; chunk = r - img * BPI0; n = 80 * 16384; heat = h0; }
    else if (bid < BLK01) { layer = 1; int r = bid - BLK0;  img = r / BPI1; chunk = r - img * BPI1; n = 80 * 4096;  heat = h1; }
    else                  { layer = 2; int r = bid - BLK01; img = r / BPI2; chunk = r - img * BPI2; n = 80 * 1024;  heat = h2; }
    int bl = img * NL + layer;
    float thr = c_thr[layer];
    unsigned int tb = __float_as_uint(thr);

    const float4* p = reinterpret_cast<const float4*>(heat + (size_t)img * n) + chunk * (CHUNK / 4);
    unsigned int base_idx = (unsigned int)chunk * CHUNK;
    int tid = threadIdx.x;

    // CHUNK/4 = 4096 float4 = 2 outer iters × 8 unrolled × 256 threads
#pragma unroll
    for (int it = 0; it < 2; it++) {
        int i0 = it * 2048 + tid;
        float4 v[8];
#pragma unroll
        for (int u = 0; u < 8; u++) v[u] = p[i0 + u * 256];   // batched independent loads
        float mx = 0.0f;
#pragma unroll
        for (int u = 0; u < 8; u++)
            mx = fmaxf(mx, fmaxf(fmaxf(v[u].x, v[u].y), fmaxf(v[u].z, v[u].w)));
        if (mx >= thr) {   // rare (~2% of threads)
#pragma unroll
            for (int u = 0; u < 8; u++) {
                unsigned int fi = base_idx + 4u * (unsigned int)(i0 + u * 256);
                try_append(__float_as_uint(v[u].x), fi + 0u, tb, bl);
                try_append(__float_as_uint(v[u].y), fi + 1u, tb, bl);
                try_append(__float_as_uint(v[u].z), fi + 2u, tb, bl);
                try_append(__float_as_uint(v[u].w), fi + 3u, tb, bl);
            }
        }
    }
}

// ---------------- register-blocked, padded bitonic sort (descending), NT threads ------
__device__ __forceinline__ void ce(unsigned long long& a, unsigned long long& b, bool dir) {
    if ((a < b) == dir) { unsigned long long t = a; a = b; b = t; }
}

template <int NT>
__device__ void bitonic_desc_opt(unsigned long long* s, int n, int tid) {
    // k = 2, 4, 8 fully in registers (8 contiguous keys per work item)
    for (int t8 = tid; t8 < (n >> 3); t8 += NT) {
        int g = t8 << 3;
        unsigned long long v[8];
#pragma unroll
        for (int x = 0; x < 8; x++) v[x] = s[SPAD(g + x)];
        ce(v[0], v[1], true);  ce(v[2], v[3], false);
        ce(v[4], v[5], true);  ce(v[6], v[7], false);
        ce(v[0], v[2], true);  ce(v[1], v[3], true);
        ce(v[4], v[6], false); ce(v[5], v[7], false);
        ce(v[0], v[1], true);  ce(v[2], v[3], true);
        ce(v[4], v[5], false); ce(v[6], v[7], false);
        bool d8 = ((g & 8) == 0);
        ce(v[0], v[4], d8); ce(v[1], v[5], d8); ce(v[2], v[6], d8); ce(v[3], v[7], d8);
        ce(v[0], v[2], d8); ce(v[1], v[3], d8); ce(v[4], v[6], d8); ce(v[5], v[7], d8);
        ce(v[0], v[1], d8); ce(v[2], v[3], d8); ce(v[4], v[5], d8); ce(v[6], v[7], d8);
#pragma unroll
        for (int x = 0; x < 8; x++) s[SPAD(g + x)] = v[x];
    }
    __syncthreads();

    for (int k = 16; k <= n; k <<= 1) {
        for (int j = k >> 1; j >= 8; j >>= 1) {
            for (int idx = tid; idx < (n >> 1); idx += NT) {
                int i = ((idx & ~(j - 1)) << 1) | (idx & (j - 1));
                int p = i + j;
                bool dir = ((i & k) == 0);
                unsigned long long a = s[SPAD(i)], b = s[SPAD(p)];
                if ((a < b) == dir) { s[SPAD(i)] = b; s[SPAD(p)] = a; }
            }
            __syncthreads();
        }
        for (int t8 = tid; t8 < (n >> 3); t8 += NT) {
            int g = t8 << 3;
            bool dir = ((g & k) == 0);
            unsigned long long v[8];
#pragma unroll
            for (int x = 0; x < 8; x++) v[x] = s[SPAD(g + x)];
            ce(v[0], v[4], dir); ce(v[1], v[5], dir); ce(v[2], v[6], dir); ce(v[3], v[7], dir);
            ce(v[0], v[2], dir); ce(v[1], v[3], dir); ce(v[4], v[6], dir); ce(v[5], v[7], dir);
            ce(v[0], v[1], dir); ce(v[2], v[3], dir); ce(v[4], v[5], dir); ce(v[6], v[7], dir);
#pragma unroll
            for (int x = 0; x < 8; x++) s[SPAD(g + x)] = v[x];
        }
        __syncthreads();
    }
}

// ---------------- pass 2: (gated exact fallback) + sort + decode + partition ----------
__global__ void __launch_bounds__(1024) sortdet_kernel(const float* __restrict__ h0,
                                                       const float* __restrict__ h1,
                                                       const float* __restrict__ h2,
                                                       const float* __restrict__ tl0,
                                                       const float* __restrict__ br0,
                                                       const float* __restrict__ tl1,
                                                       const float* __restrict__ br1,
                                                       const float* __restrict__ tl2,
                                                       const float* __restrict__ br2) {
    __shared__ unsigned long long s[SPAD(CAP)];
    __shared__ unsigned int sh_hist[NBINS];
    __shared__ unsigned int sh_tb;
    __shared__ int wsum[32];
    __shared__ int wtot;

    int bl = blockIdx.x, tid = threadIdx.x;
    int b = bl / NL, layer = bl % NL;

    const int   hws[3]   = {16384, 4096, 1024};
    const int   logWs[3] = {7, 6, 5};
    const float scs[3]   = {8.0f, 16.0f, 32.0f};
    int hw = hws[layer], logW = logWs[layer], K = c_K[layer];
    float scale = scs[layer];
    const float* heat = (layer == 0) ? h0 : (layer == 1) ? h1 : h2;
    const float* tl   = (layer == 0) ? tl0 : (layer == 1) ? tl1 : tl2;
    const float* br   = (layer == 0) ? br0 : (layer == 1) ? br1 : br2;
    int n_layer = 80 * hw;

    unsigned int cnt = g_cnt[bl];
    if (cnt < (unsigned int)K || cnt > CAP) {
        // -------- exact fallback, fully within this block --------
        for (int i = tid; i < NBINS; i += 1024) sh_hist[i] = 0u;
        __syncthreads();
        const float4* p = reinterpret_cast<const float4*>(heat + (size_t)b * n_layer);
        int n4 = n_layer >> 2;
        for (int i = tid; i < n4; i += 1024) {
            float4 v = p[i];
            atomicAdd(&sh_hist[bin_of(__float_as_uint(v.x))], 1u);
            atomicAdd(&sh_hist[bin_of(__float_as_uint(v.y))], 1u);
            atomicAdd(&sh_hist[bin_of(__float_as_uint(v.z))], 1u);
            atomicAdd(&sh_hist[bin_of(__float_as_uint(v.w))], 1u);
        }
        __syncthreads();
        if (tid == 0) {
            int bidx = NBINS - 1;
            unsigned int cum = 0;
            while (true) {
                cum += sh_hist[bidx];
                if (cum >= (unsigned int)K || bidx == 0) break;
                --bidx;
            }
            unsigned int lb;
            if (bidx >= 1150)     lb = 0x3F800000u;
            else if (bidx >= 126) lb = 0x3F000000u + ((unsigned int)(bidx - 126) << 13);
            else                  lb = ((unsigned int)bidx) << 23;
            sh_tb = lb;
            g_cnt[bl] = 0u;
        }
        __syncthreads();
        unsigned int tb = sh_tb;
        for (int i = tid; i < n4; i += 1024) {
            float4 v = p[i];
            unsigned int fi = 4u * (unsigned int)i;
            try_append(__float_as_uint(v.x), fi + 0u, tb, bl);
            try_append(__float_as_uint(v.y), fi + 1u, tb, bl);
            try_append(__float_as_uint(v.z), fi + 2u, tb, bl);
            try_append(__float_as_uint(v.w), fi + 3u, tb, bl);
        }
        __syncthreads();
        cnt = g_cnt[bl];
    }

    int m = (cnt > (unsigned int)CAP) ? CAP : (int)cnt;
    int n = (m <= 2048) ? 2048 : CAP;   // K <= 2048 always

    for (int i = tid; i < n; i += 1024)
        s[SPAD(i)] = (i < m) ? g_cand[bl][i] : 0ull;
    __syncthreads();

    bitonic_desc_opt<1024>(s, n, tid);
    // s[0..K-1] = exact sorted top-K: value desc, index asc on ties.

    const float* tlp = tl + (size_t)b * 2 * hw;
    const float* brp = br + (size_t)b * 2 * hw;
    int Wm1 = (1 << logW) - 1;

    float sc_[2], d1[2], d2[2], d3[2], d4[2];
    int flag[2];
    int tsum = 0;
#pragma unroll
    for (int u = 0; u < 2; u++) {
        int r = tid * 2 + u;
        flag[u] = 0;
        if (r < K) {
            unsigned long long key = s[SPAD(r)];
            unsigned int bits = (unsigned int)(key >> 32);
            unsigned int idx  = ~(unsigned int)key;
            int sp = (int)(idx & (unsigned int)(hw - 1));
            float fy = (float)(sp >> logW);
            float fx = (float)(sp & Wm1);
            float tx = tlp[sp], ty = tlp[hw + sp];
            float bx = brp[sp], by = brp[hw + sp];
            float tlx = fx - fmaf(1.5f, tx, 2.25f);
            float tly = fy - fmaf(1.5f, ty, 2.25f);
            float brx = fx + fmaf(1.5f, bx, 2.25f);
            float bry = fy + fmaf(1.5f, by, 2.25f);
            bool valid = !((brx < tlx) || (bry < tly));
            flag[u] = valid ? 1 : 0;
            sc_[u] = valid ? __uint_as_float(bits) : -1.0f;
            d1[u] = tlx * scale; d2[u] = tly * scale;
            d3[u] = brx * scale; d4[u] = bry * scale;
            tsum += flag[u];
        }
    }

    // block exclusive scan of valid flags (thread t owns ranks 2t, 2t+1)
    int lane = tid & 31, warp = tid >> 5;
    int incl = tsum;
#pragma unroll
    for (int off = 1; off < 32; off <<= 1) {
        int t2 = __shfl_up_sync(0xffffffffu, incl, off);
        if (lane >= off) incl += t2;
    }
    if (lane == 31) wsum[warp] = incl;
    __syncthreads();
    if (tid < 32) {
        int v = wsum[tid];
#pragma unroll
        for (int off = 1; off < 32; off <<= 1) {
            int t2 = __shfl_up_sync(0xffffffffu, v, off);
            if (lane >= off) v += t2;
        }
        wsum[tid] = v;
        if (tid == 31) wtot = v;
    }
    __syncthreads();

    int total_valid = wtot;
    int run = (warp ? wsum[warp - 1] : 0) + (incl - tsum);
#pragma unroll
    for (int u = 0; u < 2; u++) {
        int r = tid * 2 + u;
        if (r < K) {
            int pos = flag[u] ? run : (total_valid + (r - run));
            if (pos < ND) {
                float* d = g_det[b][layer][pos];
                d[0] = sc_[u]; d[1] = d1[u]; d[2] = d2[u];
                d[3] = d3[u];  d[4] = d4[u]; d[5] = 0.0f; d[6] = 0.0f;
            }
            run += flag[u];
        }
    }
    __syncthreads();
    if (tid < 7) g_det[b][layer][6][tid] = (float)layer;   // det.at[:,6,:] = layer
    if (tid == 0) g_cnt[bl] = 0u;                          // reset for next replay
}

// ---------------- pass 3: 3-way sorted merge by ranking (no sort) ----------------
// Each per-layer segment is descending in key except the row-6 overwrite; treat it as
// a sorted 999-list with a hole at index 6 plus one singleton. Keys are unique.
__global__ void __launch_bounds__(1024) final_kernel(float* __restrict__ out) {
    __shared__ unsigned long long keys[NL * ND];
    __shared__ unsigned long long ovk[NL];
    int b = blockIdx.x, tid = threadIdx.x;

    for (int i = tid; i < NL * ND; i += 1024) {
        int l = i / ND, r = i - l * ND;
        unsigned int sb = __float_as_uint(g_det[b][l][r][0]);
        unsigned int mp = (sb & 0x80000000u) ? ~sb : (sb | 0x80000000u);  // monotone map
        keys[i] = ((unsigned long long)mp << 32) | (unsigned int)(~(unsigned int)i);
    }
    __syncthreads();
    if (tid < NL) ovk[tid] = keys[tid * ND + 6];
    __syncthreads();

    for (int e = tid; e < NL * ND; e += 1024) {
        unsigned long long my = keys[e];
        int rank = 0;
#pragma unroll
        for (int l = 0; l < NL; l++) {
            // count strictly greater in holed (999-elem) descending list of segment l
            int lo = 0, hi = ND - 1;
            int base = l * ND;
            while (lo < hi) {
                int mid = (lo + hi) >> 1;
                int ph = mid + (mid >= 6);
                if (keys[base + ph] > my) lo = mid + 1; else hi = mid;
            }
            rank += lo + (ovk[l] > my ? 1 : 0);
        }
        if (rank < ND) {
            int l = e / ND, r = e - l * ND;
            const float* src = g_det[b][l][r];
            float* dst = out + ((size_t)b * ND + rank) * 7;
#pragma unroll
            for (int c = 0; c < 7; c++) dst[c] = src[c];
        }
    }
}

extern "C" void kernel_launch(void* const* d_in, const int* in_sizes, int n_in,
                              void* d_out, int out_size) {
    const int hw[3] = {16384, 4096, 1024};

    // Resolve inputs BY SIZE (metadata order is heat0, tl0, br0, heat1, ...).
    const float* heat[3] = {0, 0, 0};
    const float* tl[3]   = {0, 0, 0};
    const float* br[3]   = {0, 0, 0};
    for (int i = 0; i < n_in; i++) {
        long long sz = in_sizes[i];
        for (int l = 0; l < 3; l++) {
            if (sz == (long long)BATCH * 80 * hw[l]) {
                heat[l] = (const float*)d_in[i];
            } else if (sz == (long long)BATCH * 2 * hw[l]) {
                if (!tl[l]) tl[l] = (const float*)d_in[i];
                else        br[l] = (const float*)d_in[i];
            }
        }
    }

    collectA_kernel<<<BLKALL, 256>>>(heat[0], heat[1], heat[2]);
    sortdet_kernel<<<NBL, 1024>>>(heat[0], heat[1], heat[2],
                                  tl[0], br[0], tl[1], br[1], tl[2], br[2]);
    final_kernel<<<BATCH, 1024>>>((float*)d_out);
}

// round 8
// speedup vs baseline: 2.9959x; 1.2057x over previous
#include <cuda_runtime.h>

#define BATCH 16
#define NL 3
#define NBL (BATCH * NL)
#define NBINS 1152
#define CAP 4096
#define ND 1000
#define CHUNK 16384
#define SPAD(i) ((i) + ((i) >> 3))   // bank-conflict padding for u64 shared arrays

// grid layout for collectA (per-layer chunk counts)
#define BPI0 80
#define BPI1 20
#define BPI2 5
#define BLK0 (BATCH * BPI0)              // 1280
#define BLK01 (BLK0 + BATCH * BPI1)      // 1600
#define BLKALL (BLK01 + BATCH * BPI2)    // 1680

// ---------------- persistent scratch (zero at load; self-resetting each replay) -------
__device__ unsigned int       g_cnt[NBL];   // zeroed by sortdet at end of each replay
__device__ unsigned long long g_cand[NBL][CAP];
__device__ float              g_det[BATCH][NL][ND][7];

__constant__ float c_thr[3] = {1.0f - 3000.0f / 1310720.0f,
                               1.0f - 3000.0f / 327680.0f,
                               1.0f - 1500.0f / 81920.0f};
__constant__ int   c_K[3]   = {2000, 2000, 1024};

// Monotone bin mapping (fallback path only): fine bins over [0.5,1).
__device__ __forceinline__ int bin_of(unsigned int bits) {
    if (bits >= 0x3F800000u) return 1150;
    if (bits >= 0x3F000000u) return 126 + (int)((bits - 0x3F000000u) >> 13);
    return (int)(bits >> 23);
}

// ---------------- pass 1: single-pass collect with static thresholds ----------------
// Hot loop: 8 independent coalesced LDG.128 per thread per iteration, no warp votes.
// Hits buffered in shared; ONE global atomic per block (kills per-address LTS
// serialization that capped R6/R7 at ~1.35 TB/s).
__global__ void __launch_bounds__(256) collectA_kernel(const float* __restrict__ h0,
                                                       const float* __restrict__ h1,
                                                       const float* __restrict__ h2) {
    __shared__ unsigned long long s_buf[CAP];
    __shared__ unsigned int s_cnt;
    __shared__ unsigned int s_base;

    int bid = blockIdx.x, layer, img, chunk, n;
    const float* heat;
    if (bid < BLK0)       { layer = 0; int r = bid;         img = r / BPI0; chunk = r - img * BPI0; n = 80 * 16384; heat = h0; }
    else if (bid < BLK01) { layer = 1; int r = bid - BLK0;  img = r / BPI1; chunk = r - img * BPI1; n = 80 * 4096;  heat = h1; }
    else                  { layer = 2; int r = bid - BLK01; img = r / BPI2; chunk = r - img * BPI2; n = 80 * 1024;  heat = h2; }
    int bl = img * NL + layer;
    float thr = c_thr[layer];
    unsigned int tb = __float_as_uint(thr);

    int tid = threadIdx.x;
    if (tid == 0) s_cnt = 0u;
    __syncthreads();

    const float4* p = reinterpret_cast<const float4*>(heat + (size_t)img * n) + chunk * (CHUNK / 4);
    unsigned int base_idx = (unsigned int)chunk * CHUNK;

    // CHUNK/4 = 4096 float4 = 2 outer iters × 8 unrolled × 256 threads
#pragma unroll
    for (int it = 0; it < 2; it++) {
        int i0 = it * 2048 + tid;
        float4 v[8];
#pragma unroll
        for (int u = 0; u < 8; u++) v[u] = p[i0 + u * 256];   // batched independent loads
        float mx = 0.0f;
#pragma unroll
        for (int u = 0; u < 8; u++)
            mx = fmaxf(mx, fmaxf(fmaxf(v[u].x, v[u].y), fmaxf(v[u].z, v[u].w)));
        if (mx >= thr) {   // rare (~2% of threads)
#pragma unroll
            for (int u = 0; u < 8; u++) {
                unsigned int fi = base_idx + 4u * (unsigned int)(i0 + u * 256);
                float vv[4] = {v[u].x, v[u].y, v[u].z, v[u].w};
#pragma unroll
                for (int c = 0; c < 4; c++) {
                    unsigned int bits = __float_as_uint(vv[c]);
                    if (bits >= tb) {
                        unsigned int pos = atomicAdd(&s_cnt, 1u);
                        if (pos < CAP)
                            s_buf[pos] = ((unsigned long long)bits << 32)
                                       | (unsigned int)(~(fi + (unsigned int)c));
                    }
                }
            }
        }
    }
    __syncthreads();

    unsigned int cnt = s_cnt;
    if (cnt == 0u) return;
    if (tid == 0) s_base = atomicAdd(&g_cnt[bl], cnt);  // one global atomic per block
    __syncthreads();

    unsigned int nloc = (cnt > CAP) ? CAP : cnt;        // local overflow => total > CAP => fallback
    unsigned int base = s_base;
    for (unsigned int i = tid; i < nloc; i += 256) {
        unsigned int g = base + i;
        if (g < CAP) g_cand[bl][g] = s_buf[i];
    }
}

// ---------------- register-blocked, padded bitonic sort (descending), NT threads ------
__device__ __forceinline__ void ce(unsigned long long& a, unsigned long long& b, bool dir) {
    if ((a < b) == dir) { unsigned long long t = a; a = b; b = t; }
}

template <int NT>
__device__ void bitonic_desc_opt(unsigned long long* s, int n, int tid) {
    // k = 2, 4, 8 fully in registers (8 contiguous keys per work item)
    for (int t8 = tid; t8 < (n >> 3); t8 += NT) {
        int g = t8 << 3;
        unsigned long long v[8];
#pragma unroll
        for (int x = 0; x < 8; x++) v[x] = s[SPAD(g + x)];
        ce(v[0], v[1], true);  ce(v[2], v[3], false);
        ce(v[4], v[5], true);  ce(v[6], v[7], false);
        ce(v[0], v[2], true);  ce(v[1], v[3], true);
        ce(v[4], v[6], false); ce(v[5], v[7], false);
        ce(v[0], v[1], true);  ce(v[2], v[3], true);
        ce(v[4], v[5], false); ce(v[6], v[7], false);
        bool d8 = ((g & 8) == 0);
        ce(v[0], v[4], d8); ce(v[1], v[5], d8); ce(v[2], v[6], d8); ce(v[3], v[7], d8);
        ce(v[0], v[2], d8); ce(v[1], v[3], d8); ce(v[4], v[6], d8); ce(v[5], v[7], d8);
        ce(v[0], v[1], d8); ce(v[2], v[3], d8); ce(v[4], v[5], d8); ce(v[6], v[7], d8);
#pragma unroll
        for (int x = 0; x < 8; x++) s[SPAD(g + x)] = v[x];
    }
    __syncthreads();

    for (int k = 16; k <= n; k <<= 1) {
        for (int j = k >> 1; j >= 8; j >>= 1) {
            for (int idx = tid; idx < (n >> 1); idx += NT) {
                int i = ((idx & ~(j - 1)) << 1) | (idx & (j - 1));
                int p = i + j;
                bool dir = ((i & k) == 0);
                unsigned long long a = s[SPAD(i)], b = s[SPAD(p)];
                if ((a < b) == dir) { s[SPAD(i)] = b; s[SPAD(p)] = a; }
            }
            __syncthreads();
        }
        for (int t8 = tid; t8 < (n >> 3); t8 += NT) {
            int g = t8 << 3;
            bool dir = ((g & k) == 0);
            unsigned long long v[8];
#pragma unroll
            for (int x = 0; x < 8; x++) v[x] = s[SPAD(g + x)];
            ce(v[0], v[4], dir); ce(v[1], v[5], dir); ce(v[2], v[6], dir); ce(v[3], v[7], dir);
            ce(v[0], v[2], dir); ce(v[1], v[3], dir); ce(v[4], v[6], dir); ce(v[5], v[7], dir);
            ce(v[0], v[1], dir); ce(v[2], v[3], dir); ce(v[4], v[5], dir); ce(v[6], v[7], dir);
#pragma unroll
            for (int x = 0; x < 8; x++) s[SPAD(g + x)] = v[x];
        }
        __syncthreads();
    }
}

// ---------------- pass 2: (gated exact fallback) + sort + decode + partition ----------
__global__ void __launch_bounds__(1024) sortdet_kernel(const float* __restrict__ h0,
                                                       const float* __restrict__ h1,
                                                       const float* __restrict__ h2,
                                                       const float* __restrict__ tl0,
                                                       const float* __restrict__ br0,
                                                       const float* __restrict__ tl1,
                                                       const float* __restrict__ br1,
                                                       const float* __restrict__ tl2,
                                                       const float* __restrict__ br2) {
    __shared__ unsigned long long s[SPAD(CAP)];
    __shared__ unsigned int sh_hist[NBINS];
    __shared__ unsigned int sh_tb;
    __shared__ int wsum[32];
    __shared__ int wtot;

    int bl = blockIdx.x, tid = threadIdx.x;
    int b = bl / NL, layer = bl % NL;

    const int   hws[3]   = {16384, 4096, 1024};
    const int   logWs[3] = {7, 6, 5};
    const float scs[3]   = {8.0f, 16.0f, 32.0f};
    int hw = hws[layer], logW = logWs[layer], K = c_K[layer];
    float scale = scs[layer];
    const float* heat = (layer == 0) ? h0 : (layer == 1) ? h1 : h2;
    const float* tl   = (layer == 0) ? tl0 : (layer == 1) ? tl1 : tl2;
    const float* br   = (layer == 0) ? br0 : (layer == 1) ? br1 : br2;
    int n_layer = 80 * hw;

    unsigned int cnt = g_cnt[bl];
    if (cnt < (unsigned int)K || cnt > CAP) {
        // -------- exact fallback, fully within this block --------
        for (int i = tid; i < NBINS; i += 1024) sh_hist[i] = 0u;
        __syncthreads();
        const float4* p = reinterpret_cast<const float4*>(heat + (size_t)b * n_layer);
        int n4 = n_layer >> 2;
        for (int i = tid; i < n4; i += 1024) {
            float4 v = p[i];
            atomicAdd(&sh_hist[bin_of(__float_as_uint(v.x))], 1u);
            atomicAdd(&sh_hist[bin_of(__float_as_uint(v.y))], 1u);
            atomicAdd(&sh_hist[bin_of(__float_as_uint(v.z))], 1u);
            atomicAdd(&sh_hist[bin_of(__float_as_uint(v.w))], 1u);
        }
        __syncthreads();
        if (tid == 0) {
            int bidx = NBINS - 1;
            unsigned int cum = 0;
            while (true) {
                cum += sh_hist[bidx];
                if (cum >= (unsigned int)K || bidx == 0) break;
                --bidx;
            }
            unsigned int lb;
            if (bidx >= 1150)     lb = 0x3F800000u;
            else if (bidx >= 126) lb = 0x3F000000u + ((unsigned int)(bidx - 126) << 13);
            else                  lb = ((unsigned int)bidx) << 23;
            sh_tb = lb;
            g_cnt[bl] = 0u;
        }
        __syncthreads();
        unsigned int tb = sh_tb;
        for (int i = tid; i < n4; i += 1024) {
            float4 v = p[i];
            unsigned int fi = 4u * (unsigned int)i;
            float vv[4] = {v.x, v.y, v.z, v.w};
#pragma unroll
            for (int c = 0; c < 4; c++) {
                unsigned int bits = __float_as_uint(vv[c]);
                if (bits >= tb) {
                    unsigned int pos = atomicAdd(&g_cnt[bl], 1u);
                    if (pos < CAP)
                        g_cand[bl][pos] = ((unsigned long long)bits << 32)
                                        | (unsigned int)(~(fi + (unsigned int)c));
                }
            }
        }
        __syncthreads();
        cnt = g_cnt[bl];
    }

    int m = (cnt > (unsigned int)CAP) ? CAP : (int)cnt;
    int n = (m <= 2048) ? 2048 : CAP;   // K <= 2048 always

    for (int i = tid; i < n; i += 1024)
        s[SPAD(i)] = (i < m) ? g_cand[bl][i] : 0ull;
    __syncthreads();

    bitonic_desc_opt<1024>(s, n, tid);
    // s[0..K-1] = exact sorted top-K: value desc, index asc on ties.

    const float* tlp = tl + (size_t)b * 2 * hw;
    const float* brp = br + (size_t)b * 2 * hw;
    int Wm1 = (1 << logW) - 1;

    float sc_[2], d1[2], d2[2], d3[2], d4[2];
    int flag[2];
    int tsum = 0;
#pragma unroll
    for (int u = 0; u < 2; u++) {
        int r = tid * 2 + u;
        flag[u] = 0;
        if (r < K) {
            unsigned long long key = s[SPAD(r)];
            unsigned int bits = (unsigned int)(key >> 32);
            unsigned int idx  = ~(unsigned int)key;
            int sp = (int)(idx & (unsigned int)(hw - 1));
            float fy = (float)(sp >> logW);
            float fx = (float)(sp & Wm1);
            float tx = tlp[sp], ty = tlp[hw + sp];
            float bx = brp[sp], by = brp[hw + sp];
            float tlx = fx - fmaf(1.5f, tx, 2.25f);
            float tly = fy - fmaf(1.5f, ty, 2.25f);
            float brx = fx + fmaf(1.5f, bx, 2.25f);
            float bry = fy + fmaf(1.5f, by, 2.25f);
            bool valid = !((brx < tlx) || (bry < tly));
            flag[u] = valid ? 1 : 0;
            sc_[u] = valid ? __uint_as_float(bits) : -1.0f;
            d1[u] = tlx * scale; d2[u] = tly * scale;
            d3[u] = brx * scale; d4[u] = bry * scale;
            tsum += flag[u];
        }
    }

    // block exclusive scan of valid flags (thread t owns ranks 2t, 2t+1)
    int lane = tid & 31, warp = tid >> 5;
    int incl = tsum;
#pragma unroll
    for (int off = 1; off < 32; off <<= 1) {
        int t2 = __shfl_up_sync(0xffffffffu, incl, off);
        if (lane >= off) incl += t2;
    }
    if (lane == 31) wsum[warp] = incl;
    __syncthreads();
    if (tid < 32) {
        int v = wsum[tid];
#pragma unroll
        for (int off = 1; off < 32; off <<= 1) {
            int t2 = __shfl_up_sync(0xffffffffu, v, off);
            if (lane >= off) v += t2;
        }
        wsum[tid] = v;
        if (tid == 31) wtot = v;
    }
    __syncthreads();

    int total_valid = wtot;
    int run = (warp ? wsum[warp - 1] : 0) + (incl - tsum);
#pragma unroll
    for (int u = 0; u < 2; u++) {
        int r = tid * 2 + u;
        if (r < K) {
            int pos = flag[u] ? run : (total_valid + (r - run));
            if (pos < ND) {
                float* d = g_det[b][layer][pos];
                d[0] = sc_[u]; d[1] = d1[u]; d[2] = d2[u];
                d[3] = d3[u];  d[4] = d4[u]; d[5] = 0.0f; d[6] = 0.0f;
            }
            run += flag[u];
        }
    }
    __syncthreads();
    if (tid < 7) g_det[b][layer][6][tid] = (float)layer;   // det.at[:,6,:] = layer
    if (tid == 0) g_cnt[bl] = 0u;                          // reset for next replay
}

// ---------------- pass 3: 3-way sorted merge by ranking (no sort) ----------------
// Each per-layer segment is descending in key except the row-6 overwrite; treat it as
// a sorted 999-list with a hole at index 6 plus one singleton. Keys are unique.
__global__ void __launch_bounds__(1024) final_kernel(float* __restrict__ out) {
    __shared__ unsigned long long keys[NL * ND];
    __shared__ unsigned long long ovk[NL];
    int b = blockIdx.x, tid = threadIdx.x;

    for (int i = tid; i < NL * ND; i += 1024) {
        int l = i / ND, r = i - l * ND;
        unsigned int sb = __float_as_uint(g_det[b][l][r][0]);
        unsigned int mp = (sb & 0x80000000u) ? ~sb : (sb | 0x80000000u);  // monotone map
        keys[i] = ((unsigned long long)mp << 32) | (unsigned int)(~(unsigned int)i);
    }
    __syncthreads();
    if (tid < NL) ovk[tid] = keys[tid * ND + 6];
    __syncthreads();

    for (int e = tid; e < NL * ND; e += 1024) {
        unsigned long long my = keys[e];
        int rank = 0;
#pragma unroll
        for (int l = 0; l < NL; l++) {
            // count strictly greater in holed (999-elem) descending list of segment l
            int lo = 0, hi = ND - 1;
            int base = l * ND;
            while (lo < hi) {
                int mid = (lo + hi) >> 1;
                int ph = mid + (mid >= 6);
                if (keys[base + ph] > my) lo = mid + 1; else hi = mid;
            }
            rank += lo + (ovk[l] > my ? 1 : 0);
        }
        if (rank < ND) {
            int l = e / ND, r = e - l * ND;
            const float* src = g_det[b][l][r];
            float* dst = out + ((size_t)b * ND + rank) * 7;
#pragma unroll
            for (int c = 0; c < 7; c++) dst[c] = src[c];
        }
    }
}

extern "C" void kernel_launch(void* const* d_in, const int* in_sizes, int n_in,
                              void* d_out, int out_size) {
    const int hw[3] = {16384, 4096, 1024};

    // Resolve inputs BY SIZE (metadata order is heat0, tl0, br0, heat1, ...).
    const float* heat[3] = {0, 0, 0};
    const float* tl[3]   = {0, 0, 0};
    const float* br[3]   = {0, 0, 0};
    for (int i = 0; i < n_in; i++) {
        long long sz = in_sizes[i];
        for (int l = 0; l < 3; l++) {
            if (sz == (long long)BATCH * 80 * hw[l]) {
                heat[l] = (const float*)d_in[i];
            } else if (sz == (long long)BATCH * 2 * hw[l]) {
                if (!tl[l]) tl[l] = (const float*)d_in[i];
                else        br[l] = (const float*)d_in[i];
            }
        }
    }

    collectA_kernel<<<BLKALL, 256>>>(heat[0], heat[1], heat[2]);
    sortdet_kernel<<<NBL, 1024>>>(heat[0], heat[1], heat[2],
                                  tl[0], br[0], tl[1], br[1], tl[2], br[2]);
    final_kernel<<<BATCH, 1024>>>((float*)d_out);
}

// round 9
// speedup vs baseline: 5.1410x; 1.7160x over previous
#include <cuda_runtime.h>

#define BATCH 16
#define NL 3
#define NBL (BATCH * NL)
#define NBINS 1152
#define CAP 4096
#define SBUF 512
#define ND 1000
#define CHUNK 16384
#define SPAD(i) ((i) + ((i) >> 3))   // bank-conflict padding for u64 shared arrays

// grid layout for collectA (per-layer chunk counts)
#define BPI0 80
#define BPI1 20
#define BPI2 5
#define BLK0 (BATCH * BPI0)              // 1280
#define BLK01 (BLK0 + BATCH * BPI1)      // 1600
#define BLKALL (BLK01 + BATCH * BPI2)    // 1680

// ---------------- persistent scratch (zero at load; self-resetting each replay) -------
__device__ unsigned int       g_cnt[NBL];   // zeroed by sortdet at end of each replay
__device__ unsigned long long g_cand[NBL][CAP];
__device__ float              g_det[BATCH][NL][ND][7];

__constant__ float c_thr[3] = {1.0f - 3000.0f / 1310720.0f,
                               1.0f - 3000.0f / 327680.0f,
                               1.0f - 1500.0f / 81920.0f};
__constant__ int   c_K[3]      = {2000, 2000, 1024};
__constant__ int   c_shift[3]  = {6, 8, 9};   // selection histogram bin shift per layer

// Monotone bin mapping (fallback path only): fine bins over [0.5,1).
__device__ __forceinline__ int bin_of(unsigned int bits) {
    if (bits >= 0x3F800000u) return 1150;
    if (bits >= 0x3F000000u) return 126 + (int)((bits - 0x3F000000u) >> 13);
    return (int)(bits >> 23);
}

// ---------------- pass 1: single-pass collect with static thresholds ----------------
// 4 independent coalesced LDG.128 per thread per iter; 32-reg cap for full occupancy.
// Hits staged in a small smem buffer; ONE global atomic per block.
__global__ void __launch_bounds__(256, 8) collectA_kernel(const float* __restrict__ h0,
                                                          const float* __restrict__ h1,
                                                          const float* __restrict__ h2) {
    __shared__ unsigned long long s_buf[SBUF];
    __shared__ unsigned int s_cnt;
    __shared__ unsigned int s_base;

    int bid = blockIdx.x, layer, img, chunk, n;
    const float* heat;
    if (bid < BLK0)       { layer = 0; int r = bid;         img = r / BPI0; chunk = r - img * BPI0; n = 80 * 16384; heat = h0; }
    else if (bid < BLK01) { layer = 1; int r = bid - BLK0;  img = r / BPI1; chunk = r - img * BPI1; n = 80 * 4096;  heat = h1; }
    else                  { layer = 2; int r = bid - BLK01; img = r / BPI2; chunk = r - img * BPI2; n = 80 * 1024;  heat = h2; }
    int bl = img * NL + layer;
    float thr = c_thr[layer];
    unsigned int tb = __float_as_uint(thr);

    int tid = threadIdx.x;
    if (tid == 0) s_cnt = 0u;
    __syncthreads();

    const float4* p = reinterpret_cast<const float4*>(heat + (size_t)img * n) + chunk * (CHUNK / 4);
    unsigned int base_idx = (unsigned int)chunk * CHUNK;

    // CHUNK/4 = 4096 float4 = 4 outer iters × 4 unrolled × 256 threads
#pragma unroll
    for (int it = 0; it < 4; it++) {
        int i0 = it * 1024 + tid;
        float4 v[4];
#pragma unroll
        for (int u = 0; u < 4; u++) v[u] = p[i0 + u * 256];   // batched independent loads
        float mx = 0.0f;
#pragma unroll
        for (int u = 0; u < 4; u++)
            mx = fmaxf(mx, fmaxf(fmaxf(v[u].x, v[u].y), fmaxf(v[u].z, v[u].w)));
        if (mx >= thr) {   // rare (~1% of threads)
#pragma unroll
            for (int u = 0; u < 4; u++) {
                unsigned int fi = base_idx + 4u * (unsigned int)(i0 + u * 256);
                float vv[4] = {v[u].x, v[u].y, v[u].z, v[u].w};
#pragma unroll
                for (int c = 0; c < 4; c++) {
                    unsigned int bits = __float_as_uint(vv[c]);
                    if (bits >= tb) {
                        unsigned int pos = atomicAdd(&s_cnt, 1u);
                        if (pos < SBUF)
                            s_buf[pos] = ((unsigned long long)bits << 32)
                                       | (unsigned int)(~(fi + (unsigned int)c));
                    }
                }
            }
        }
    }
    __syncthreads();

    unsigned int cnt = s_cnt;
    if (cnt == 0u) return;
    if (tid == 0) {
        // local overflow: force total past CAP so the exact fallback fires
        s_base = atomicAdd(&g_cnt[bl], (cnt > SBUF) ? (CAP + 1u) : cnt);
    }
    __syncthreads();
    if (cnt > SBUF) return;

    unsigned int base = s_base;
    for (unsigned int i = tid; i < cnt; i += 256) {
        unsigned int g = base + i;
        if (g < CAP) g_cand[bl][g] = s_buf[i];
    }
}

// ---------------- register-blocked, padded bitonic sort (descending), NT threads ------
__device__ __forceinline__ void ce(unsigned long long& a, unsigned long long& b, bool dir) {
    if ((a < b) == dir) { unsigned long long t = a; a = b; b = t; }
}

template <int NT>
__device__ void bitonic_desc_opt(unsigned long long* s, int n, int tid) {
    // k = 2, 4, 8 fully in registers (8 contiguous keys per work item)
    for (int t8 = tid; t8 < (n >> 3); t8 += NT) {
        int g = t8 << 3;
        unsigned long long v[8];
#pragma unroll
        for (int x = 0; x < 8; x++) v[x] = s[SPAD(g + x)];
        ce(v[0], v[1], true);  ce(v[2], v[3], false);
        ce(v[4], v[5], true);  ce(v[6], v[7], false);
        ce(v[0], v[2], true);  ce(v[1], v[3], true);
        ce(v[4], v[6], false); ce(v[5], v[7], false);
        ce(v[0], v[1], true);  ce(v[2], v[3], true);
        ce(v[4], v[5], false); ce(v[6], v[7], false);
        bool d8 = ((g & 8) == 0);
        ce(v[0], v[4], d8); ce(v[1], v[5], d8); ce(v[2], v[6], d8); ce(v[3], v[7], d8);
        ce(v[0], v[2], d8); ce(v[1], v[3], d8); ce(v[4], v[6], d8); ce(v[5], v[7], d8);
        ce(v[0], v[1], d8); ce(v[2], v[3], d8); ce(v[4], v[5], d8); ce(v[6], v[7], d8);
#pragma unroll
        for (int x = 0; x < 8; x++) s[SPAD(g + x)] = v[x];
    }
    __syncthreads();

    for (int k = 16; k <= n; k <<= 1) {
        for (int j = k >> 1; j >= 8; j >>= 1) {
            for (int idx = tid; idx < (n >> 1); idx += NT) {
                int i = ((idx & ~(j - 1)) << 1) | (idx & (j - 1));
                int p = i + j;
                bool dir = ((i & k) == 0);
                unsigned long long a = s[SPAD(i)], b = s[SPAD(p)];
                if ((a < b) == dir) { s[SPAD(i)] = b; s[SPAD(p)] = a; }
            }
            __syncthreads();
        }
        for (int t8 = tid; t8 < (n >> 3); t8 += NT) {
            int g = t8 << 3;
            bool dir = ((g & k) == 0);
            unsigned long long v[8];
#pragma unroll
            for (int x = 0; x < 8; x++) v[x] = s[SPAD(g + x)];
            ce(v[0], v[4], dir); ce(v[1], v[5], dir); ce(v[2], v[6], dir); ce(v[3], v[7], dir);
            ce(v[0], v[2], dir); ce(v[1], v[3], dir); ce(v[4], v[6], dir); ce(v[5], v[7], dir);
            ce(v[0], v[1], dir); ce(v[2], v[3], dir); ce(v[4], v[5], dir); ce(v[6], v[7], dir);
#pragma unroll
            for (int x = 0; x < 8; x++) s[SPAD(g + x)] = v[x];
        }
        __syncthreads();
    }
}

// ---------------- pass 2: (fallback) + top-2048 selection + sort + decode -------------
__global__ void __launch_bounds__(1024) sortdet_kernel(const float* __restrict__ h0,
                                                       const float* __restrict__ h1,
                                                       const float* __restrict__ h2,
                                                       const float* __restrict__ tl0,
                                                       const float* __restrict__ br0,
                                                       const float* __restrict__ tl1,
                                                       const float* __restrict__ br1,
                                                       const float* __restrict__ tl2,
                                                       const float* __restrict__ br2) {
    __shared__ unsigned long long s[SPAD(CAP)];
    __shared__ unsigned int sh_hist[NBINS];      // reused: fallback hist / selection hist
    __shared__ unsigned int sh_tb, sh_scnt, sh_cut, sh_total;
    __shared__ int wsum[32];
    __shared__ int wtot;

    int bl = blockIdx.x, tid = threadIdx.x;
    int b = bl / NL, layer = bl % NL;

    const int   hws[3]   = {16384, 4096, 1024};
    const int   logWs[3] = {7, 6, 5};
    const float scs[3]   = {8.0f, 16.0f, 32.0f};
    int hw = hws[layer], logW = logWs[layer], K = c_K[layer];
    float scale = scs[layer];
    const float* heat = (layer == 0) ? h0 : (layer == 1) ? h1 : h2;
    const float* tl   = (layer == 0) ? tl0 : (layer == 1) ? tl1 : tl2;
    const float* br   = (layer == 0) ? br0 : (layer == 1) ? br1 : br2;
    int n_layer = 80 * hw;

    unsigned int cnt = g_cnt[bl];
    if (cnt < (unsigned int)K || cnt > CAP) {
        // -------- exact fallback, fully within this block --------
        for (int i = tid; i < NBINS; i += 1024) sh_hist[i] = 0u;
        __syncthreads();
        const float4* p = reinterpret_cast<const float4*>(heat + (size_t)b * n_layer);
        int n4 = n_layer >> 2;
        for (int i = tid; i < n4; i += 1024) {
            float4 v = p[i];
            atomicAdd(&sh_hist[bin_of(__float_as_uint(v.x))], 1u);
            atomicAdd(&sh_hist[bin_of(__float_as_uint(v.y))], 1u);
            atomicAdd(&sh_hist[bin_of(__float_as_uint(v.z))], 1u);
            atomicAdd(&sh_hist[bin_of(__float_as_uint(v.w))], 1u);
        }
        __syncthreads();
        if (tid == 0) {
            int bidx = NBINS - 1;
            unsigned int cum = 0;
            while (true) {
                cum += sh_hist[bidx];
                if (cum >= (unsigned int)K || bidx == 0) break;
                --bidx;
            }
            unsigned int lb;
            if (bidx >= 1150)     lb = 0x3F800000u;
            else if (bidx >= 126) lb = 0x3F000000u + ((unsigned int)(bidx - 126) << 13);
            else                  lb = ((unsigned int)bidx) << 23;
            sh_tb = lb;
            g_cnt[bl] = 0u;
        }
        __syncthreads();
        unsigned int tb = sh_tb;
        for (int i = tid; i < n4; i += 1024) {
            float4 v = p[i];
            unsigned int fi = 4u * (unsigned int)i;
            float vv[4] = {v.x, v.y, v.z, v.w};
#pragma unroll
            for (int c = 0; c < 4; c++) {
                unsigned int bits = __float_as_uint(vv[c]);
                if (bits >= tb) {
                    unsigned int pos = atomicAdd(&g_cnt[bl], 1u);
                    if (pos < CAP)
                        g_cand[bl][pos] = ((unsigned long long)bits << 32)
                                        | (unsigned int)(~(fi + (unsigned int)c));
                }
            }
        }
        __syncthreads();
        cnt = g_cnt[bl];
    }

    int m = (cnt > (unsigned int)CAP) ? CAP : (int)cnt;
    int nsort;

    if (m <= 2048) {
        for (int i = tid; i < 2048; i += 1024)
            s[SPAD(i)] = (i < m) ? g_cand[bl][i] : 0ull;
        nsort = 2048;
    } else {
        // ---- exact top-(<=2048) selection by value-bin histogram ----
        int shift = c_shift[layer];
        for (int i = tid; i < 1024; i += 1024) sh_hist[i] = 0u;
        __syncthreads();
        for (int i = tid; i < m; i += 1024) {
            unsigned int bits = (unsigned int)(g_cand[bl][i] >> 32);
            int off = (int)(0x3F800000u - bits);
            int bin = (off <= 0) ? 0 : min(1023, off >> shift);
            atomicAdd(&sh_hist[bin], 1u);
        }
        __syncthreads();
        // inclusive scan of sh_hist[0..1024)
        for (int off = 1; off < 1024; off <<= 1) {
            unsigned int v = sh_hist[tid & 1023];
            unsigned int a = ((tid & 1023) >= off) ? sh_hist[(tid & 1023) - off] : 0u;
            __syncthreads();
            if (tid < 1024) sh_hist[tid] = v + a;
            __syncthreads();
        }
        if (tid < 1024) {
            unsigned int cum = sh_hist[tid];
            unsigned int prev = (tid == 0) ? 0u : sh_hist[tid - 1];
            if (cum >= (unsigned int)K && prev < (unsigned int)K) {
                sh_cut = (unsigned int)tid;
                sh_total = cum;
            }
        }
        if (tid == 0) sh_scnt = 0u;
        __syncthreads();

        if (sh_total <= 2048u) {
            unsigned int cut = sh_cut;
            for (int i = tid; i < m; i += 1024) {
                unsigned long long key = g_cand[bl][i];
                unsigned int bits = (unsigned int)(key >> 32);
                int off = (int)(0x3F800000u - bits);
                unsigned int bin = (off <= 0) ? 0u : (unsigned int)min(1023, off >> shift);
                if (bin <= cut) {
                    unsigned int pos = atomicAdd(&sh_scnt, 1u);
                    s[SPAD(pos)] = key;
                }
            }
            __syncthreads();
            unsigned int tot = sh_scnt;
            for (unsigned int i = tot + tid; i < 2048u; i += 1024u) s[SPAD(i)] = 0ull;
            nsort = 2048;
        } else {
            for (int i = tid; i < CAP; i += 1024)
                s[SPAD(i)] = (i < m) ? g_cand[bl][i] : 0ull;
            nsort = CAP;
        }
    }
    __syncthreads();

    bitonic_desc_opt<1024>(s, nsort, tid);
    // s[0..K-1] = exact sorted top-K: value desc, index asc on ties.

    const float* tlp = tl + (size_t)b * 2 * hw;
    const float* brp = br + (size_t)b * 2 * hw;
    int Wm1 = (1 << logW) - 1;

    float sc_[2], d1[2], d2[2], d3[2], d4[2];
    int flag[2];
    int tsum = 0;
#pragma unroll
    for (int u = 0; u < 2; u++) {
        int r = tid * 2 + u;
        flag[u] = 0;
        if (r < K) {
            unsigned long long key = s[SPAD(r)];
            unsigned int bits = (unsigned int)(key >> 32);
            unsigned int idx  = ~(unsigned int)key;
            int sp = (int)(idx & (unsigned int)(hw - 1));
            float fy = (float)(sp >> logW);
            float fx = (float)(sp & Wm1);
            float tx = tlp[sp], ty = tlp[hw + sp];
            float bx = brp[sp], by = brp[hw + sp];
            float tlx = fx - fmaf(1.5f, tx, 2.25f);
            float tly = fy - fmaf(1.5f, ty, 2.25f);
            float brx = fx + fmaf(1.5f, bx, 2.25f);
            float bry = fy + fmaf(1.5f, by, 2.25f);
            bool valid = !((brx < tlx) || (bry < tly));
            flag[u] = valid ? 1 : 0;
            sc_[u] = valid ? __uint_as_float(bits) : -1.0f;
            d1[u] = tlx * scale; d2[u] = tly * scale;
            d3[u] = brx * scale; d4[u] = bry * scale;
            tsum += flag[u];
        }
    }

    // block exclusive scan of valid flags (thread t owns ranks 2t, 2t+1)
    int lane = tid & 31, warp = tid >> 5;
    int incl = tsum;
#pragma unroll
    for (int off = 1; off < 32; off <<= 1) {
        int t2 = __shfl_up_sync(0xffffffffu, incl, off);
        if (lane >= off) incl += t2;
    }
    if (lane == 31) wsum[warp] = incl;
    __syncthreads();
    if (tid < 32) {
        int v = wsum[tid];
#pragma unroll
        for (int off = 1; off < 32; off <<= 1) {
            int t2 = __shfl_up_sync(0xffffffffu, v, off);
            if (lane >= off) v += t2;
        }
        wsum[tid] = v;
        if (tid == 31) wtot = v;
    }
    __syncthreads();

    int total_valid = wtot;
    int run = (warp ? wsum[warp - 1] : 0) + (incl - tsum);
#pragma unroll
    for (int u = 0; u < 2; u++) {
        int r = tid * 2 + u;
        if (r < K) {
            int pos = flag[u] ? run : (total_valid + (r - run));
            if (pos < ND) {
                float* d = g_det[b][layer][pos];
                d[0] = sc_[u]; d[1] = d1[u]; d[2] = d2[u];
                d[3] = d3[u];  d[4] = d4[u]; d[5] = 0.0f; d[6] = 0.0f;
            }
            run += flag[u];
        }
    }
    __syncthreads();
    if (tid < 7) g_det[b][layer][6][tid] = (float)layer;   // det.at[:,6,:] = layer
    if (tid == 0) g_cnt[bl] = 0u;                          // reset for next replay
}

// ---------------- pass 3: 3-way sorted merge by ranking (no sort) ----------------
__global__ void __launch_bounds__(1024) final_kernel(float* __restrict__ out) {
    __shared__ unsigned long long keys[NL * ND];
    __shared__ unsigned long long ovk[NL];
    int b = blockIdx.x, tid = threadIdx.x;

    for (int i = tid; i < NL * ND; i += 1024) {
        int l = i / ND, r = i - l * ND;
        unsigned int sb = __float_as_uint(g_det[b][l][r][0]);
        unsigned int mp = (sb & 0x80000000u) ? ~sb : (sb | 0x80000000u);  // monotone map
        keys[i] = ((unsigned long long)mp << 32) | (unsigned int)(~(unsigned int)i);
    }
    __syncthreads();
    if (tid < NL) ovk[tid] = keys[tid * ND + 6];
    __syncthreads();

    for (int e = tid; e < NL * ND; e += 1024) {
        unsigned long long my = keys[e];
        int rank = 0;
#pragma unroll
        for (int l = 0; l < NL; l++) {
            // count strictly greater in holed (999-elem) descending list of segment l
            int lo = 0, hi = ND - 1;
            int base = l * ND;
            while (lo < hi) {
                int mid = (lo + hi) >> 1;
                int ph = mid + (mid >= 6);
                if (keys[base + ph] > my) lo = mid + 1; else hi = mid;
            }
            rank += lo + (ovk[l] > my ? 1 : 0);
        }
        if (rank < ND) {
            int l = e / ND, r = e - l * ND;
            const float* src = g_det[b][l][r];
            float* dst = out + ((size_t)b * ND + rank) * 7;
#pragma unroll
            for (int c = 0; c < 7; c++) dst[c] = src[c];
        }
    }
}

extern "C" void kernel_launch(void* const* d_in, const int* in_sizes, int n_in,
                              void* d_out, int out_size) {
    const int hw[3] = {16384, 4096, 1024};

    // Resolve inputs BY SIZE (metadata order is heat0, tl0, br0, heat1, ...).
    const float* heat[3] = {0, 0, 0};
    const float* tl[3]   = {0, 0, 0};
    const float* br[3]   = {0, 0, 0};
    for (int i = 0; i < n_in; i++) {
        long long sz = in_sizes[i];
        for (int l = 0; l < 3; l++) {
            if (sz == (long long)BATCH * 80 * hw[l]) {
                heat[l] = (const float*)d_in[i];
            } else if (sz == (long long)BATCH * 2 * hw[l]) {
                if (!tl[l]) tl[l] = (const float*)d_in[i];
                else        br[l] = (const float*)d_in[i];
            }
        }
    }

    collectA_kernel<<<BLKALL, 256>>>(heat[0], heat[1], heat[2]);
    sortdet_kernel<<<NBL, 1024>>>(heat[0], heat[1], heat[2],
                                  tl[0], br[0], tl[1], br[1], tl[2], br[2]);
    final_kernel<<<BATCH, 1024>>>((float*)d_out);
}